// round 1
// baseline (speedup 1.0000x reference)
#include <cuda_runtime.h>
#include <math.h>

// ---------------------------------------------------------------------------
// Problem constants
// ---------------------------------------------------------------------------
#define BB 2
#define NN 2048
#define CC 1024
#define FF 4096
#define HH 16
#define DD 64
#define MM (BB*NN)          // 4096 rows

// ---------------------------------------------------------------------------
// Scratch (device globals: allocation-free)
// ---------------------------------------------------------------------------
__device__ float g_xn [MM*CC];
__device__ float g_q  [MM*CC];
__device__ float g_k  [MM*CC];
__device__ float g_v  [MM*CC];
__device__ float g_y  [MM*CC];
__device__ float g_x1 [MM*CC];
__device__ float g_xn2[MM*CC];
__device__ float g_h  [MM*FF];

// ---------------------------------------------------------------------------
// Packed fp32x2 helpers (B300: FFMA2 doubles fp32 throughput vs scalar FFMA)
// ---------------------------------------------------------------------------
#define DI __device__ __forceinline__

DI unsigned long long pack2(float lo, float hi) {
    unsigned long long r;
    asm("mov.b64 %0, {%1,%2};" : "=l"(r) : "f"(lo), "f"(hi));
    return r;
}
DI float2 unpack2(unsigned long long v) {
    float2 f;
    asm("mov.b64 {%0,%1}, %2;" : "=f"(f.x), "=f"(f.y) : "l"(v));
    return f;
}
DI unsigned long long fma2(unsigned long long a, unsigned long long b, unsigned long long c) {
    unsigned long long d;
    asm("fma.rn.f32x2 %0, %1, %2, %3;" : "=l"(d) : "l"(a), "l"(b), "l"(c));
    return d;
}
DI unsigned long long mul2(unsigned long long a, unsigned long long b) {
    unsigned long long d;
    asm("mul.rn.f32x2 %0, %1, %2;" : "=l"(d) : "l"(a), "l"(b));
    return d;
}

// ---------------------------------------------------------------------------
// LayerNorm: one block per row (C = 1024, 256 threads, float4 per thread)
// ---------------------------------------------------------------------------
__global__ __launch_bounds__(256)
void ln_kernel(const float* __restrict__ x, const float* __restrict__ gamma,
               const float* __restrict__ beta, float* __restrict__ out)
{
    const int row = blockIdx.x;
    const int tid = threadIdx.x;
    const float4* xr = reinterpret_cast<const float4*>(x + (size_t)row * CC);
    float4 v = xr[tid];

    float s  = v.x + v.y + v.z + v.w;
    float sq = v.x*v.x + v.y*v.y + v.z*v.z + v.w*v.w;

    #pragma unroll
    for (int o = 16; o > 0; o >>= 1) {
        s  += __shfl_xor_sync(0xFFFFFFFFu, s,  o);
        sq += __shfl_xor_sync(0xFFFFFFFFu, sq, o);
    }
    __shared__ float sh_s[8], sh_q[8];
    __shared__ float sh_mu, sh_inv;
    const int warp = tid >> 5, lane = tid & 31;
    if (lane == 0) { sh_s[warp] = s; sh_q[warp] = sq; }
    __syncthreads();
    if (tid == 0) {
        float S = 0.f, Q = 0.f;
        #pragma unroll
        for (int i = 0; i < 8; i++) { S += sh_s[i]; Q += sh_q[i]; }
        const float mu  = S * (1.0f / CC);
        const float var = Q * (1.0f / CC) - mu * mu;
        sh_mu  = mu;
        sh_inv = rsqrtf(var + 1e-6f);
    }
    __syncthreads();
    const float mu = sh_mu, inv = sh_inv;
    const float4 g = reinterpret_cast<const float4*>(gamma)[tid];
    const float4 b = reinterpret_cast<const float4*>(beta)[tid];
    float4 o;
    o.x = (v.x - mu) * inv * g.x + b.x;
    o.y = (v.y - mu) * inv * g.y + b.y;
    o.z = (v.z - mu) * inv * g.z + b.z;
    o.w = (v.w - mu) * inv * g.w + b.w;
    reinterpret_cast<float4*>(out + (size_t)row * CC)[tid] = o;
}

// ---------------------------------------------------------------------------
// SGEMM: C(MxN) = epilogue(A(MxK) @ B(KxN))
// 128x128 block tile, BK=8, 256 threads, 8x8 per-thread tile held as 8x4
// packed f32x2 accumulators. Double-buffered smem.
// MODE 0: out = alpha * acc
// MODE 1: out = acc + bias[n] + res[m][n]
// MODE 2: out = gelu_exact(acc + bias[n])
// ---------------------------------------------------------------------------
template<int MODE>
__global__ __launch_bounds__(256)
void sgemm_kernel(const float* __restrict__ A, const float* __restrict__ B,
                  float* __restrict__ Cmat, int M, int N, int K,
                  float alpha, const float* __restrict__ bias,
                  const float* __restrict__ res)
{
    __shared__ __align__(16) float As[2][8][128];
    __shared__ __align__(16) float Bs[2][8][128];

    const int tid = threadIdx.x;
    const int bm = blockIdx.y * 128;
    const int bn = blockIdx.x * 128;

    const int arow = tid >> 1;            // 0..127
    const int acol = (tid & 1) << 2;      // 0 or 4
    const int brow = tid >> 5;            // 0..7
    const int bcol = (tid & 31) << 2;     // 0..124

    const float* Ap = A + (size_t)(bm + arow) * K + acol;
    const float* Bp = B + (size_t)brow * N + (bn + bcol);

    const int tx = tid & 15;
    const int ty = tid >> 4;

    unsigned long long acc[8][4];
    #pragma unroll
    for (int i = 0; i < 8; i++)
        #pragma unroll
        for (int j = 0; j < 4; j++) acc[i][j] = 0ULL;

    // preload tile 0
    {
        float4 av = *reinterpret_cast<const float4*>(Ap);
        float4 bv = *reinterpret_cast<const float4*>(Bp);
        As[0][acol+0][arow] = av.x; As[0][acol+1][arow] = av.y;
        As[0][acol+2][arow] = av.z; As[0][acol+3][arow] = av.w;
        *reinterpret_cast<float4*>(&Bs[0][brow][bcol]) = bv;
    }
    __syncthreads();

    int buf = 0;
    for (int kt = 0; kt < K; kt += 8) {
        float4 av, bv;
        const bool has_next = (kt + 8) < K;
        if (has_next) {
            av = *reinterpret_cast<const float4*>(Ap + (kt + 8));
            bv = *reinterpret_cast<const float4*>(Bp + (size_t)(kt + 8) * N);
        }
        #pragma unroll
        for (int kk = 0; kk < 8; kk++) {
            const float4 a0 = *reinterpret_cast<const float4*>(&As[buf][kk][ty * 8]);
            const float4 a1 = *reinterpret_cast<const float4*>(&As[buf][kk][ty * 8 + 4]);
            const ulonglong2 b01 = *reinterpret_cast<const ulonglong2*>(&Bs[buf][kk][tx * 8]);
            const ulonglong2 b23 = *reinterpret_cast<const ulonglong2*>(&Bs[buf][kk][tx * 8 + 4]);
            const unsigned long long b2[4] = { b01.x, b01.y, b23.x, b23.y };
            const float a[8] = { a0.x, a0.y, a0.z, a0.w, a1.x, a1.y, a1.z, a1.w };
            #pragma unroll
            for (int i = 0; i < 8; i++) {
                const unsigned long long ar = pack2(a[i], a[i]);
                #pragma unroll
                for (int j = 0; j < 4; j++)
                    acc[i][j] = fma2(ar, b2[j], acc[i][j]);
            }
        }
        if (has_next) {
            const int nb = buf ^ 1;
            As[nb][acol+0][arow] = av.x; As[nb][acol+1][arow] = av.y;
            As[nb][acol+2][arow] = av.z; As[nb][acol+3][arow] = av.w;
            *reinterpret_cast<float4*>(&Bs[nb][brow][bcol]) = bv;
            __syncthreads();
        }
        buf ^= 1;
    }

    const int row0 = bm + ty * 8;
    const int col0 = bn + tx * 8;
    #pragma unroll
    for (int i = 0; i < 8; i++) {
        const size_t rbase = (size_t)(row0 + i) * N;
        #pragma unroll
        for (int j = 0; j < 4; j++) {
            float2 v = unpack2(acc[i][j]);
            const int c = col0 + 2 * j;
            if (MODE == 0) {
                v.x *= alpha; v.y *= alpha;
            } else if (MODE == 1) {
                const float2 rv = *reinterpret_cast<const float2*>(&res[rbase + c]);
                v.x += bias[c]     + rv.x;
                v.y += bias[c + 1] + rv.y;
            } else { // MODE 2: exact GELU
                v.x += bias[c]; v.y += bias[c + 1];
                v.x = 0.5f * v.x * (1.0f + erff(v.x * 0.70710678118654752f));
                v.y = 0.5f * v.y * (1.0f + erff(v.y * 0.70710678118654752f));
            }
            *reinterpret_cast<float2*>(&Cmat[rbase + c]) = v;
        }
    }
}

// ---------------------------------------------------------------------------
// Flash-style attention (fp32, online softmax).
// Grid: (N/128, H, B). 128 threads; each thread owns one query row
// (q and o live in packed f32x2 registers). K/V tiles of TK=32 rows staged
// in smem, read back as broadcast ulonglong2 (LDS.128) so the smem crossbar
// stays well under the fma-pipe time.
// Q is pre-scaled by D^-0.5 (alpha of the Q GEMM).
// ---------------------------------------------------------------------------
#define TK 32
__global__ __launch_bounds__(128)
void attn_kernel(const float* __restrict__ Q, const float* __restrict__ Kt,
                 const float* __restrict__ Vt, float* __restrict__ Y)
{
    const int h = blockIdx.y, b = blockIdx.z;
    const int tid  = threadIdx.x;
    const int lane = tid & 31, warp = tid >> 5;
    const int qrow = blockIdx.x * 128 + tid;

    __shared__ __align__(16) float Ks[TK][DD];
    __shared__ __align__(16) float Vs[TK][DD];
    __shared__ __align__(16) float Ss[TK][128];

    const size_t head_base = ((size_t)b * NN) * CC + (size_t)h * DD;

    unsigned long long q2[32], o2[32];
    {
        const unsigned long long* qr =
            reinterpret_cast<const unsigned long long*>(Q + head_base + (size_t)qrow * CC);
        #pragma unroll
        for (int i = 0; i < 32; i++) { q2[i] = qr[i]; o2[i] = 0ULL; }
    }

    float mrun = -1e30f, lrun = 0.f;

    for (int kt = 0; kt < NN; kt += TK) {
        __syncthreads();
        // cooperative, coalesced K/V tile load: warp per row group, float2/lane
        #pragma unroll
        for (int r = warp; r < TK; r += 4) {
            const float2* ks = reinterpret_cast<const float2*>(Kt + head_base + (size_t)(kt + r) * CC);
            const float2* vs = reinterpret_cast<const float2*>(Vt + head_base + (size_t)(kt + r) * CC);
            reinterpret_cast<float2*>(&Ks[r][0])[lane] = ks[lane];
            reinterpret_cast<float2*>(&Vs[r][0])[lane] = vs[lane];
        }
        __syncthreads();

        // scores for this tile
        float mtile = mrun;
        #pragma unroll 4
        for (int j = 0; j < TK; j++) {
            unsigned long long acc0 = 0ULL, acc1 = 0ULL;
            const ulonglong2* kr = reinterpret_cast<const ulonglong2*>(&Ks[j][0]);
            #pragma unroll
            for (int dp = 0; dp < 16; dp++) {
                const ulonglong2 kk2 = kr[dp];
                acc0 = fma2(q2[2*dp],   kk2.x, acc0);
                acc1 = fma2(q2[2*dp+1], kk2.y, acc1);
            }
            const float2 f0 = unpack2(acc0), f1 = unpack2(acc1);
            const float s = (f0.x + f0.y) + (f1.x + f1.y);
            Ss[j][tid] = s;
            mtile = fmaxf(mtile, s);
        }

        // rescale running state
        const float corr = __expf(mrun - mtile);
        lrun *= corr;
        const unsigned long long c2 = pack2(corr, corr);
        #pragma unroll
        for (int i = 0; i < 32; i++) o2[i] = mul2(o2[i], c2);

        // accumulate P @ V
        #pragma unroll 4
        for (int j = 0; j < TK; j++) {
            const float p = __expf(Ss[j][tid] - mtile);
            lrun += p;
            const unsigned long long p2 = pack2(p, p);
            const ulonglong2* vr = reinterpret_cast<const ulonglong2*>(&Vs[j][0]);
            #pragma unroll
            for (int dp = 0; dp < 16; dp++) {
                const ulonglong2 vv = vr[dp];
                o2[2*dp]   = fma2(p2, vv.x, o2[2*dp]);
                o2[2*dp+1] = fma2(p2, vv.y, o2[2*dp+1]);
            }
        }
        mrun = mtile;
    }

    const float invl = 1.0f / lrun;
    const unsigned long long i2 = pack2(invl, invl);
    float2* yr = reinterpret_cast<float2*>(Y + head_base + (size_t)qrow * CC);
    #pragma unroll
    for (int dp = 0; dp < 32; dp++)
        yr[dp] = unpack2(mul2(o2[dp], i2));
}

// ---------------------------------------------------------------------------
// Launch
// ---------------------------------------------------------------------------
extern "C" void kernel_launch(void* const* d_in, const int* in_sizes, int n_in,
                              void* d_out, int out_size)
{
    const float* x      = (const float*)d_in[0];
    const float* Wq     = (const float*)d_in[1];
    const float* Wk     = (const float*)d_in[2];
    const float* Wv     = (const float*)d_in[3];
    const float* Wp     = (const float*)d_in[4];
    const float* bp     = (const float*)d_in[5];
    const float* W1     = (const float*)d_in[6];
    const float* b1     = (const float*)d_in[7];
    const float* W2     = (const float*)d_in[8];
    const float* b2     = (const float*)d_in[9];
    const float* gamma1 = (const float*)d_in[10];
    const float* beta1  = (const float*)d_in[11];
    const float* gamma2 = (const float*)d_in[12];
    const float* beta2  = (const float*)d_in[13];
    float* out = (float*)d_out;

    float *xn, *q, *k, *v, *y, *x1, *xn2, *hbuf;
    cudaGetSymbolAddress((void**)&xn,   g_xn);
    cudaGetSymbolAddress((void**)&q,    g_q);
    cudaGetSymbolAddress((void**)&k,    g_k);
    cudaGetSymbolAddress((void**)&v,    g_v);
    cudaGetSymbolAddress((void**)&y,    g_y);
    cudaGetSymbolAddress((void**)&x1,   g_x1);
    cudaGetSymbolAddress((void**)&xn2,  g_xn2);
    cudaGetSymbolAddress((void**)&hbuf, g_h);

    const float scale = 0.125f;  // D^-0.5, D = 64

    const dim3 gC(CC / 128, MM / 128);   // (8, 32)
    const dim3 gF(FF / 128, MM / 128);   // (32, 32)

    // 1) LN1
    ln_kernel<<<MM, 256>>>(x, gamma1, beta1, xn);
    // 2) QKV projections (Q pre-scaled)
    sgemm_kernel<0><<<gC, 256>>>(xn, Wq, q, MM, CC, CC, scale, nullptr, nullptr);
    sgemm_kernel<0><<<gC, 256>>>(xn, Wk, k, MM, CC, CC, 1.0f,  nullptr, nullptr);
    sgemm_kernel<0><<<gC, 256>>>(xn, Wv, v, MM, CC, CC, 1.0f,  nullptr, nullptr);
    // 3) attention
    attn_kernel<<<dim3(NN / 128, HH, BB), 128>>>(q, k, v, y);
    // 4) x1 = x + y @ Wp + bp
    sgemm_kernel<1><<<gC, 256>>>(y, Wp, x1, MM, CC, CC, 1.0f, bp, x);
    // 5) LN2
    ln_kernel<<<MM, 256>>>(x1, gamma2, beta2, xn2);
    // 6) h = gelu(xn2 @ W1 + b1)
    sgemm_kernel<2><<<gF, 256>>>(xn2, W1, hbuf, MM, FF, CC, 1.0f, b1, nullptr);
    // 7) out = x1 + h @ W2 + b2
    sgemm_kernel<1><<<gC, 256>>>(hbuf, W2, out, MM, CC, FF, 1.0f, b2, x1);
}

// round 6
// speedup vs baseline: 1.6231x; 1.6231x over previous
#include <cuda_runtime.h>
#include <math.h>
#include <stdint.h>

// ---------------------------------------------------------------------------
// Problem constants
// ---------------------------------------------------------------------------
#define BB 2
#define NN 2048
#define CC 1024
#define FF 4096
#define HH 16
#define DD 64
#define MM (BB*NN)          // 4096 rows

// ---------------------------------------------------------------------------
// Scratch (device globals: allocation-free)
// ---------------------------------------------------------------------------
__device__ float g_xn [MM*CC];
__device__ float g_q  [MM*CC];
__device__ float g_k  [MM*CC];
__device__ float g_v  [MM*CC];
__device__ float g_y  [MM*CC];
__device__ float g_x1 [MM*CC];
__device__ float g_xn2[MM*CC];
__device__ float g_h  [MM*FF];
// transposed weights ([N,K], K-contiguous rows)
__device__ float g_wqT[CC*CC];
__device__ float g_wkT[CC*CC];
__device__ float g_wvT[CC*CC];
__device__ float g_wpT[CC*CC];
__device__ float g_w1T[CC*FF];
__device__ float g_w2T[CC*FF];

#define DI __device__ __forceinline__

// ---------------------------------------------------------------------------
// Packed fp32x2 helpers (FFMA2 attention kernel)
// ---------------------------------------------------------------------------
DI unsigned long long pack2(float lo, float hi) {
    unsigned long long r;
    asm("mov.b64 %0, {%1,%2};" : "=l"(r) : "f"(lo), "f"(hi));
    return r;
}
DI float2 unpack2(unsigned long long v) {
    float2 f;
    asm("mov.b64 {%0,%1}, %2;" : "=f"(f.x), "=f"(f.y) : "l"(v));
    return f;
}
DI unsigned long long fma2(unsigned long long a, unsigned long long b, unsigned long long c) {
    unsigned long long d;
    asm("fma.rn.f32x2 %0, %1, %2, %3;" : "=l"(d) : "l"(a), "l"(b), "l"(c));
    return d;
}
DI unsigned long long mul2(unsigned long long a, unsigned long long b) {
    unsigned long long d;
    asm("mul.rn.f32x2 %0, %1, %2;" : "=l"(d) : "l"(a), "l"(b));
    return d;
}

// ---------------------------------------------------------------------------
// tf32 helpers (mma.sync path — arch-portable, works on non-'a' PTX target)
// ---------------------------------------------------------------------------
DI uint32_t f2tf32(float x) {
    uint32_t r;
    asm("cvt.rna.tf32.f32 %0, %1;" : "=r"(r) : "f"(x));
    return r;
}
DI void mma_tf32(float* d, const uint32_t* a, const uint32_t* b) {
    asm volatile(
        "mma.sync.aligned.m16n8k8.row.col.f32.tf32.tf32.f32 "
        "{%0,%1,%2,%3}, {%4,%5,%6,%7}, {%8,%9}, {%0,%1,%2,%3};"
        : "+f"(d[0]), "+f"(d[1]), "+f"(d[2]), "+f"(d[3])
        : "r"(a[0]), "r"(a[1]), "r"(a[2]), "r"(a[3]), "r"(b[0]), "r"(b[1]));
}

// ---------------------------------------------------------------------------
// LayerNorm: one block per row
// ---------------------------------------------------------------------------
__global__ __launch_bounds__(256)
void ln_kernel(const float* __restrict__ x, const float* __restrict__ gamma,
               const float* __restrict__ beta, float* __restrict__ out)
{
    const int row = blockIdx.x;
    const int tid = threadIdx.x;
    const float4* xr = reinterpret_cast<const float4*>(x + (size_t)row * CC);
    float4 v = xr[tid];

    float s  = v.x + v.y + v.z + v.w;
    float sq = v.x*v.x + v.y*v.y + v.z*v.z + v.w*v.w;

    #pragma unroll
    for (int o = 16; o > 0; o >>= 1) {
        s  += __shfl_xor_sync(0xFFFFFFFFu, s,  o);
        sq += __shfl_xor_sync(0xFFFFFFFFu, sq, o);
    }
    __shared__ float sh_s[8], sh_q[8];
    __shared__ float sh_mu, sh_inv;
    const int warp = tid >> 5, lane = tid & 31;
    if (lane == 0) { sh_s[warp] = s; sh_q[warp] = sq; }
    __syncthreads();
    if (tid == 0) {
        float S = 0.f, Q = 0.f;
        #pragma unroll
        for (int i = 0; i < 8; i++) { S += sh_s[i]; Q += sh_q[i]; }
        const float mu  = S * (1.0f / CC);
        const float var = Q * (1.0f / CC) - mu * mu;
        sh_mu  = mu;
        sh_inv = rsqrtf(var + 1e-6f);
    }
    __syncthreads();
    const float mu = sh_mu, inv = sh_inv;
    const float4 g = reinterpret_cast<const float4*>(gamma)[tid];
    const float4 b = reinterpret_cast<const float4*>(beta)[tid];
    float4 o;
    o.x = (v.x - mu) * inv * g.x + b.x;
    o.y = (v.y - mu) * inv * g.y + b.y;
    o.z = (v.z - mu) * inv * g.z + b.z;
    o.w = (v.w - mu) * inv * g.w + b.w;
    reinterpret_cast<float4*>(out + (size_t)row * CC)[tid] = o;
}

// ---------------------------------------------------------------------------
// Weight transpose: out[C x R] = in[R x C]^T
// ---------------------------------------------------------------------------
__global__ __launch_bounds__(256)
void transpose_kernel(const float* __restrict__ in, float* __restrict__ out,
                      int R, int C)
{
    __shared__ float t[32][33];
    const int bx = blockIdx.x * 32;
    const int by = blockIdx.y * 32;
    const int tx = threadIdx.x, ty = threadIdx.y;
    #pragma unroll
    for (int i = ty; i < 32; i += 8)
        t[i][tx] = in[(size_t)(by + i) * C + (bx + tx)];
    __syncthreads();
    #pragma unroll
    for (int i = ty; i < 32; i += 8)
        out[(size_t)(bx + i) * R + (by + tx)] = t[tx][i];
}

// ---------------------------------------------------------------------------
// tf32 mma.sync GEMM: C[M,N] = epi(A[M,K] @ Bt[N,K]^T)
// 128x128 CTA tile, BK=16, 8 warps (2m x 4n), each warp 64x32 via
// m16n8k8 tf32 mma (4 m-frags x 4 n-frags). Padded smem (stride 20 words:
// conflict-free for both fragment read patterns), register-double-buffered.
// MODE 0: out = alpha*acc   MODE 1: out = acc + bias[n] + res[m][n]
// MODE 2: out = gelu_exact(acc + bias[n])
// ---------------------------------------------------------------------------
#define BKT 16
#define STR 20   // smem row stride in words (row*80B: 16B-aligned, bank-clean)

template<int MODE>
__global__ __launch_bounds__(256)
void mma_gemm(const float* __restrict__ A, const float* __restrict__ Bt,
              float* __restrict__ Cmat, int M, int N, int K,
              float alpha, const float* __restrict__ bias,
              const float* __restrict__ res)
{
    __shared__ __align__(16) uint32_t As[2][128 * STR];
    __shared__ __align__(16) uint32_t Bs[2][128 * STR];

    const int tid  = threadIdx.x;
    const int wid  = tid >> 5, lane = tid & 31;
    const int m0 = blockIdx.y * 128;
    const int n0 = blockIdx.x * 128;
    const int wm = (wid >> 2) * 64;     // warp m offset
    const int wn = (wid & 3) * 32;      // warp n offset
    const int g  = lane >> 2;           // 0..7
    const int t4 = lane & 3;            // 0..3

    float acc[4][4][4];
    #pragma unroll
    for (int mf = 0; mf < 4; mf++)
        #pragma unroll
        for (int nf = 0; nf < 4; nf++)
            #pragma unroll
            for (int r = 0; r < 4; r++) acc[mf][nf][r] = 0.f;

    // loader: 2 float4 per matrix per thread per tile
    const int lr = tid >> 2;            // 0..63 (+64 for it=1)
    const int lc = (tid & 3) * 4;       // 0,4,8,12

    const float* Ap = A  + (size_t)(m0 + lr) * K + lc;
    const float* Bp = Bt + (size_t)(n0 + lr) * K + lc;

    float4 av[2], bv[2];

    // preload tile 0
    #pragma unroll
    for (int it = 0; it < 2; it++) {
        av[it] = *reinterpret_cast<const float4*>(Ap + (size_t)it * 64 * K);
        bv[it] = *reinterpret_cast<const float4*>(Bp + (size_t)it * 64 * K);
    }
    #pragma unroll
    for (int it = 0; it < 2; it++) {
        const int off = (lr + it * 64) * STR + lc;
        uint32_t* as = &As[0][off];
        uint32_t* bs = &Bs[0][off];
        as[0]=f2tf32(av[it].x); as[1]=f2tf32(av[it].y);
        as[2]=f2tf32(av[it].z); as[3]=f2tf32(av[it].w);
        bs[0]=f2tf32(bv[it].x); bs[1]=f2tf32(bv[it].y);
        bs[2]=f2tf32(bv[it].z); bs[3]=f2tf32(bv[it].w);
    }
    __syncthreads();

    int buf = 0;
    for (int kt = 0; kt < K; kt += BKT) {
        const bool has_next = (kt + BKT) < K;
        if (has_next) {
            #pragma unroll
            for (int it = 0; it < 2; it++) {
                av[it] = *reinterpret_cast<const float4*>(Ap + (size_t)it * 64 * K + kt + BKT);
                bv[it] = *reinterpret_cast<const float4*>(Bp + (size_t)it * 64 * K + kt + BKT);
            }
        }
        // compute on buf
        #pragma unroll
        for (int ks = 0; ks < BKT; ks += 8) {
            uint32_t afr[4][4], bfr[4][2];
            #pragma unroll
            for (int mf = 0; mf < 4; mf++) {
                const int r0 = wm + mf * 16 + g;
                afr[mf][0] = As[buf][r0 * STR + ks + t4];
                afr[mf][1] = As[buf][(r0 + 8) * STR + ks + t4];
                afr[mf][2] = As[buf][r0 * STR + ks + t4 + 4];
                afr[mf][3] = As[buf][(r0 + 8) * STR + ks + t4 + 4];
            }
            #pragma unroll
            for (int nf = 0; nf < 4; nf++) {
                const int nr = wn + nf * 8 + g;
                bfr[nf][0] = Bs[buf][nr * STR + ks + t4];
                bfr[nf][1] = Bs[buf][nr * STR + ks + t4 + 4];
            }
            #pragma unroll
            for (int mf = 0; mf < 4; mf++)
                #pragma unroll
                for (int nf = 0; nf < 4; nf++)
                    mma_tf32(acc[mf][nf], afr[mf], bfr[nf]);
        }
        if (has_next) {
            const int nb = buf ^ 1;
            #pragma unroll
            for (int it = 0; it < 2; it++) {
                const int off = (lr + it * 64) * STR + lc;
                uint32_t* as = &As[nb][off];
                uint32_t* bs = &Bs[nb][off];
                as[0]=f2tf32(av[it].x); as[1]=f2tf32(av[it].y);
                as[2]=f2tf32(av[it].z); as[3]=f2tf32(av[it].w);
                bs[0]=f2tf32(bv[it].x); bs[1]=f2tf32(bv[it].y);
                bs[2]=f2tf32(bv[it].z); bs[3]=f2tf32(bv[it].w);
            }
        }
        __syncthreads();
        buf ^= 1;
    }

    // epilogue: thread holds (row g / g+8, cols 2*t4, 2*t4+1) per frag
    #pragma unroll
    for (int mf = 0; mf < 4; mf++) {
        #pragma unroll
        for (int half = 0; half < 2; half++) {
            const int row = m0 + wm + mf * 16 + g + half * 8;
            float* crow = Cmat + (size_t)row * N;
            const float* rrow = (MODE == 1) ? (res + (size_t)row * N) : (const float*)0;
            #pragma unroll
            for (int nf = 0; nf < 4; nf++) {
                const int c = n0 + wn + nf * 8 + 2 * t4;
                float2 v;
                v.x = acc[mf][nf][half * 2 + 0];
                v.y = acc[mf][nf][half * 2 + 1];
                if (MODE == 0) {
                    v.x *= alpha; v.y *= alpha;
                } else if (MODE == 1) {
                    const float2 r2 = *reinterpret_cast<const float2*>(&rrow[c]);
                    v.x += bias[c]     + r2.x;
                    v.y += bias[c + 1] + r2.y;
                } else {
                    v.x += bias[c]; v.y += bias[c + 1];
                    v.x = 0.5f * v.x * (1.0f + erff(v.x * 0.70710678118654752f));
                    v.y = 0.5f * v.y * (1.0f + erff(v.y * 0.70710678118654752f));
                }
                *reinterpret_cast<float2*>(&crow[c]) = v;
            }
        }
    }
}

// ---------------------------------------------------------------------------
// Flash-style attention (fp32 FFMA2, online softmax)
// ---------------------------------------------------------------------------
#define TK 32
__global__ __launch_bounds__(128)
void attn_kernel(const float* __restrict__ Q, const float* __restrict__ Kt,
                 const float* __restrict__ Vt, float* __restrict__ Y)
{
    const int h = blockIdx.y, b = blockIdx.z;
    const int tid  = threadIdx.x;
    const int lane = tid & 31, warp = tid >> 5;
    const int qrow = blockIdx.x * 128 + tid;

    __shared__ __align__(16) float Ks[TK][DD];
    __shared__ __align__(16) float Vs[TK][DD];
    __shared__ __align__(16) float Ss[TK][128];

    const size_t head_base = ((size_t)b * NN) * CC + (size_t)h * DD;

    unsigned long long q2[32], o2[32];
    {
        const unsigned long long* qr =
            reinterpret_cast<const unsigned long long*>(Q + head_base + (size_t)qrow * CC);
        #pragma unroll
        for (int i = 0; i < 32; i++) { q2[i] = qr[i]; o2[i] = 0ULL; }
    }

    float mrun = -1e30f, lrun = 0.f;

    for (int kt = 0; kt < NN; kt += TK) {
        __syncthreads();
        #pragma unroll
        for (int r = warp; r < TK; r += 4) {
            const float2* ks = reinterpret_cast<const float2*>(Kt + head_base + (size_t)(kt + r) * CC);
            const float2* vs = reinterpret_cast<const float2*>(Vt + head_base + (size_t)(kt + r) * CC);
            reinterpret_cast<float2*>(&Ks[r][0])[lane] = ks[lane];
            reinterpret_cast<float2*>(&Vs[r][0])[lane] = vs[lane];
        }
        __syncthreads();

        float mtile = mrun;
        #pragma unroll 4
        for (int j = 0; j < TK; j++) {
            unsigned long long acc0 = 0ULL, acc1 = 0ULL;
            const ulonglong2* kr = reinterpret_cast<const ulonglong2*>(&Ks[j][0]);
            #pragma unroll
            for (int dp = 0; dp < 16; dp++) {
                const ulonglong2 kk2 = kr[dp];
                acc0 = fma2(q2[2*dp],   kk2.x, acc0);
                acc1 = fma2(q2[2*dp+1], kk2.y, acc1);
            }
            const float2 f0 = unpack2(acc0), f1 = unpack2(acc1);
            const float s = (f0.x + f0.y) + (f1.x + f1.y);
            Ss[j][tid] = s;
            mtile = fmaxf(mtile, s);
        }

        const float corr = __expf(mrun - mtile);
        lrun *= corr;
        const unsigned long long c2 = pack2(corr, corr);
        #pragma unroll
        for (int i = 0; i < 32; i++) o2[i] = mul2(o2[i], c2);

        #pragma unroll 4
        for (int j = 0; j < TK; j++) {
            const float p = __expf(Ss[j][tid] - mtile);
            lrun += p;
            const unsigned long long p2 = pack2(p, p);
            const ulonglong2* vr = reinterpret_cast<const ulonglong2*>(&Vs[j][0]);
            #pragma unroll
            for (int dp = 0; dp < 16; dp++) {
                const ulonglong2 vv = vr[dp];
                o2[2*dp]   = fma2(p2, vv.x, o2[2*dp]);
                o2[2*dp+1] = fma2(p2, vv.y, o2[2*dp+1]);
            }
        }
        mrun = mtile;
    }

    const float invl = 1.0f / lrun;
    const unsigned long long i2 = pack2(invl, invl);
    float2* yr = reinterpret_cast<float2*>(Y + head_base + (size_t)qrow * CC);
    #pragma unroll
    for (int dp = 0; dp < 32; dp++)
        yr[dp] = unpack2(mul2(o2[dp], i2));
}

// ---------------------------------------------------------------------------
// Launch
// ---------------------------------------------------------------------------
extern "C" void kernel_launch(void* const* d_in, const int* in_sizes, int n_in,
                              void* d_out, int out_size)
{
    const float* x      = (const float*)d_in[0];
    const float* Wq     = (const float*)d_in[1];
    const float* Wk     = (const float*)d_in[2];
    const float* Wv     = (const float*)d_in[3];
    const float* Wp     = (const float*)d_in[4];
    const float* bp     = (const float*)d_in[5];
    const float* W1     = (const float*)d_in[6];
    const float* b1     = (const float*)d_in[7];
    const float* W2     = (const float*)d_in[8];
    const float* b2     = (const float*)d_in[9];
    const float* gamma1 = (const float*)d_in[10];
    const float* beta1  = (const float*)d_in[11];
    const float* gamma2 = (const float*)d_in[12];
    const float* beta2  = (const float*)d_in[13];
    float* out = (float*)d_out;

    float *xn, *q, *k, *v, *y, *x1, *xn2, *hbuf;
    float *wqT, *wkT, *wvT, *wpT, *w1T, *w2T;
    cudaGetSymbolAddress((void**)&xn,   g_xn);
    cudaGetSymbolAddress((void**)&q,    g_q);
    cudaGetSymbolAddress((void**)&k,    g_k);
    cudaGetSymbolAddress((void**)&v,    g_v);
    cudaGetSymbolAddress((void**)&y,    g_y);
    cudaGetSymbolAddress((void**)&x1,   g_x1);
    cudaGetSymbolAddress((void**)&xn2,  g_xn2);
    cudaGetSymbolAddress((void**)&hbuf, g_h);
    cudaGetSymbolAddress((void**)&wqT,  g_wqT);
    cudaGetSymbolAddress((void**)&wkT,  g_wkT);
    cudaGetSymbolAddress((void**)&wvT,  g_wvT);
    cudaGetSymbolAddress((void**)&wpT,  g_wpT);
    cudaGetSymbolAddress((void**)&w1T,  g_w1T);
    cudaGetSymbolAddress((void**)&w2T,  g_w2T);

    const float scale = 0.125f;  // D^-0.5, D = 64

    // weight transposes: in [R,C] -> out [C,R]
    dim3 tb(32, 8);
    transpose_kernel<<<dim3(CC/32, CC/32), tb>>>(Wq, wqT, CC, CC);
    transpose_kernel<<<dim3(CC/32, CC/32), tb>>>(Wk, wkT, CC, CC);
    transpose_kernel<<<dim3(CC/32, CC/32), tb>>>(Wv, wvT, CC, CC);
    transpose_kernel<<<dim3(CC/32, CC/32), tb>>>(Wp, wpT, CC, CC);
    transpose_kernel<<<dim3(FF/32, CC/32), tb>>>(W1, w1T, CC, FF);
    transpose_kernel<<<dim3(CC/32, FF/32), tb>>>(W2, w2T, FF, CC);

    const dim3 gC(CC / 128, MM / 128);   // (8, 32)
    const dim3 gF(FF / 128, MM / 128);   // (32, 32)

    // 1) LN1
    ln_kernel<<<MM, 256>>>(x, gamma1, beta1, xn);
    // 2) QKV projections (Q pre-scaled)
    mma_gemm<0><<<gC, 256>>>(xn, wqT, q, MM, CC, CC, scale, nullptr, nullptr);
    mma_gemm<0><<<gC, 256>>>(xn, wkT, k, MM, CC, CC, 1.0f,  nullptr, nullptr);
    mma_gemm<0><<<gC, 256>>>(xn, wvT, v, MM, CC, CC, 1.0f,  nullptr, nullptr);
    // 3) attention
    attn_kernel<<<dim3(NN / 128, HH, BB), 128>>>(q, k, v, y);
    // 4) x1 = x + y @ Wp + bp
    mma_gemm<1><<<gC, 256>>>(y, wpT, x1, MM, CC, CC, 1.0f, bp, x);
    // 5) LN2
    ln_kernel<<<MM, 256>>>(x1, gamma2, beta2, xn2);
    // 6) h = gelu(xn2 @ W1 + b1)
    mma_gemm<2><<<gF, 256>>>(xn2, w1T, hbuf, MM, FF, CC, 1.0f, b1, nullptr);
    // 7) out = x1 + h @ W2 + b2
    mma_gemm<1><<<gC, 256>>>(hbuf, w2T, out, MM, CC, FF, 1.0f, b2, x1);
}

// round 9
// speedup vs baseline: 2.1903x; 1.3494x over previous
#include <cuda_runtime.h>
#include <cuda_fp16.h>
#include <math.h>
#include <stdint.h>

// ---------------------------------------------------------------------------
// Problem constants
// ---------------------------------------------------------------------------
#define BB 2
#define NN 2048
#define CC 1024
#define FF 4096
#define HH 16
#define DD 64
#define MM (BB*NN)          // 4096 rows

// ---------------------------------------------------------------------------
// Scratch (device globals: allocation-free)
// ---------------------------------------------------------------------------
__device__ __half g_xn [MM*CC];
__device__ __half g_q  [MM*CC];
__device__ __half g_k  [MM*CC];
__device__ __half g_v  [MM*CC];
__device__ __half g_y  [MM*CC];
__device__ float  g_x1 [MM*CC];
__device__ __half g_xn2[MM*CC];
__device__ __half g_h  [MM*FF];
// transposed fp16 weights ([N,K], K-contiguous rows)
__device__ __half g_wqT[CC*CC];
__device__ __half g_wkT[CC*CC];
__device__ __half g_wvT[CC*CC];
__device__ __half g_wpT[CC*CC];
__device__ __half g_w1T[CC*FF];
__device__ __half g_w2T[CC*FF];

#define DI __device__ __forceinline__

// ---------------------------------------------------------------------------
// Packed fp32x2 helpers (FFMA2 attention kernel)
// ---------------------------------------------------------------------------
DI unsigned long long pack2(float lo, float hi) {
    unsigned long long r;
    asm("mov.b64 %0, {%1,%2};" : "=l"(r) : "f"(lo), "f"(hi));
    return r;
}
DI float2 unpack2(unsigned long long v) {
    float2 f;
    asm("mov.b64 {%0,%1}, %2;" : "=f"(f.x), "=f"(f.y) : "l"(v));
    return f;
}
DI unsigned long long fma2(unsigned long long a, unsigned long long b, unsigned long long c) {
    unsigned long long d;
    asm("fma.rn.f32x2 %0, %1, %2, %3;" : "=l"(d) : "l"(a), "l"(b), "l"(c));
    return d;
}
DI unsigned long long mul2(unsigned long long a, unsigned long long b) {
    unsigned long long d;
    asm("mul.rn.f32x2 %0, %1, %2;" : "=l"(d) : "l"(a), "l"(b));
    return d;
}

// ---------------------------------------------------------------------------
// fp16 mma + cp.async helpers
// ---------------------------------------------------------------------------
DI void mma_f16(float* d, uint32_t a0, uint32_t a1, uint32_t a2, uint32_t a3,
                uint32_t b0, uint32_t b1) {
    asm volatile(
        "mma.sync.aligned.m16n8k16.row.col.f32.f16.f16.f32 "
        "{%0,%1,%2,%3}, {%4,%5,%6,%7}, {%8,%9}, {%0,%1,%2,%3};"
        : "+f"(d[0]), "+f"(d[1]), "+f"(d[2]), "+f"(d[3])
        : "r"(a0), "r"(a1), "r"(a2), "r"(a3), "r"(b0), "r"(b1));
}
DI uint32_t smem_u32(const void* p) {
    uint32_t a;
    asm("{ .reg .u64 t; cvta.to.shared.u64 t, %1; cvt.u32.u64 %0, t; }"
        : "=r"(a) : "l"(p));
    return a;
}
DI void cp_async16(uint32_t smem_addr, const void* gptr) {
    asm volatile("cp.async.ca.shared.global [%0], [%1], 16;"
                 :: "r"(smem_addr), "l"(gptr));
}
DI void cp_commit() { asm volatile("cp.async.commit_group;" ::: "memory"); }
DI void cp_wait2()  { asm volatile("cp.async.wait_group 2;" ::: "memory"); }

// XOR-swizzled element offset (fp16 elems) for a [row][64k] tile, 128B rows,
// 16B granules: granule ^= (row & 7). Conflict-free for both cp.async stores
// and the fragment LDS.32 pattern (8 rows x same granule -> distinct banks).
DI int swoff(int row, int gran) { return row * 64 + (((gran) ^ (row & 7)) << 3); }

// ---------------------------------------------------------------------------
// LayerNorm: one block per row, fp32 in -> fp16 out
// ---------------------------------------------------------------------------
__global__ __launch_bounds__(256)
void ln_kernel(const float* __restrict__ x, const float* __restrict__ gamma,
               const float* __restrict__ beta, __half* __restrict__ out)
{
    const int row = blockIdx.x;
    const int tid = threadIdx.x;
    const float4* xr = reinterpret_cast<const float4*>(x + (size_t)row * CC);
    float4 v = xr[tid];

    float s  = v.x + v.y + v.z + v.w;
    float sq = v.x*v.x + v.y*v.y + v.z*v.z + v.w*v.w;

    #pragma unroll
    for (int o = 16; o > 0; o >>= 1) {
        s  += __shfl_xor_sync(0xFFFFFFFFu, s,  o);
        sq += __shfl_xor_sync(0xFFFFFFFFu, sq, o);
    }
    __shared__ float sh_s[8], sh_q[8];
    __shared__ float sh_mu, sh_inv;
    const int warp = tid >> 5, lane = tid & 31;
    if (lane == 0) { sh_s[warp] = s; sh_q[warp] = sq; }
    __syncthreads();
    if (tid == 0) {
        float S = 0.f, Q = 0.f;
        #pragma unroll
        for (int i = 0; i < 8; i++) { S += sh_s[i]; Q += sh_q[i]; }
        const float mu  = S * (1.0f / CC);
        const float var = Q * (1.0f / CC) - mu * mu;
        sh_mu  = mu;
        sh_inv = rsqrtf(var + 1e-6f);
    }
    __syncthreads();
    const float mu = sh_mu, inv = sh_inv;
    const float4 g = reinterpret_cast<const float4*>(gamma)[tid];
    const float4 b = reinterpret_cast<const float4*>(beta)[tid];
    float4 o;
    o.x = (v.x - mu) * inv * g.x + b.x;
    o.y = (v.y - mu) * inv * g.y + b.y;
    o.z = (v.z - mu) * inv * g.z + b.z;
    o.w = (v.w - mu) * inv * g.w + b.w;
    __half2 h0 = __floats2half2_rn(o.x, o.y);
    __half2 h1 = __floats2half2_rn(o.z, o.w);
    uint2 st;
    st.x = *reinterpret_cast<uint32_t*>(&h0);
    st.y = *reinterpret_cast<uint32_t*>(&h1);
    *reinterpret_cast<uint2*>(out + (size_t)row * CC + tid * 4) = st;
}

// ---------------------------------------------------------------------------
// Weight transpose + fp32->fp16 convert: out[C x R] = (half)in[R x C]^T
// ---------------------------------------------------------------------------
__global__ __launch_bounds__(256)
void transpose_h_kernel(const float* __restrict__ in, __half* __restrict__ out,
                        int R, int C)
{
    __shared__ float t[32][33];
    const int bx = blockIdx.x * 32;
    const int by = blockIdx.y * 32;
    const int tx = threadIdx.x, ty = threadIdx.y;
    #pragma unroll
    for (int i = ty; i < 32; i += 8)
        t[i][tx] = in[(size_t)(by + i) * C + (bx + tx)];
    __syncthreads();
    #pragma unroll
    for (int i = ty; i < 32; i += 8)
        out[(size_t)(bx + i) * R + (by + tx)] = __float2half(t[tx][i]);
}

// ---------------------------------------------------------------------------
// fp16 mma.sync GEMM: C[M,N] = epi(A[M,K] @ Bt[N,K]^T), fp32 accumulate.
// 128x128 CTA tile, BK=64, 8 warps (2m x 4n), warp tile 64x32,
// m16n8k16 mma, 3-stage cp.async pipeline, XOR-swizzled smem.
// MODE 0: out(half) = alpha*acc
// MODE 1: out(float) = acc + bias[n] + res[m][n]
// MODE 2: out(half) = gelu_exact(acc + bias[n])
// ---------------------------------------------------------------------------
#define BK64 64
#define STG_ELEMS 8192          // 128*64 halfs = 16KB per stage per matrix
#define SMEM_GEMM (6 * STG_ELEMS * 2)   // 3 stages x (A+B) = 96KB

template<int MODE>
__global__ __launch_bounds__(256)
void hgemm(const __half* __restrict__ A, const __half* __restrict__ Bt,
           void* __restrict__ Cout, int M, int N, int K,
           float alpha, const float* __restrict__ bias,
           const float* __restrict__ res)
{
    extern __shared__ __align__(16) __half sm[];
    __half* Asm = sm;                      // 3 stages
    __half* Bsm = sm + 3 * STG_ELEMS;      // 3 stages

    const int tid  = threadIdx.x;
    const int wid  = tid >> 5, lane = tid & 31;
    const int m0 = blockIdx.y * 128;
    const int n0 = blockIdx.x * 128;
    const int wm = (wid >> 2) * 64;
    const int wn = (wid & 3) * 32;
    const int g  = lane >> 2;
    const int t4 = lane & 3;

    float acc[4][4][4];
    #pragma unroll
    for (int mf = 0; mf < 4; mf++)
        #pragma unroll
        for (int nf = 0; nf < 4; nf++)
            #pragma unroll
            for (int r = 0; r < 4; r++) acc[mf][nf][r] = 0.f;

    const int T = K / BK64;

    // cp.async stage issue: 1024 granules per matrix, 4 per thread per matrix
    const uint32_t smA = smem_u32(Asm);
    const uint32_t smB = smem_u32(Bsm);

    #define ISSUE_STAGE(stage, kc) do {                                         \
        const uint32_t aBase = smA + (uint32_t)(stage) * STG_ELEMS * 2;         \
        const uint32_t bBase = smB + (uint32_t)(stage) * STG_ELEMS * 2;         \
        _Pragma("unroll")                                                       \
        for (int j = 0; j < 4; j++) {                                           \
            const int id = tid + j * 256;                                       \
            const int r = id >> 3, gr = id & 7;                                 \
            const int so = swoff(r, gr) * 2;                                    \
            cp_async16(aBase + so, A  + (size_t)(m0 + r) * K + (kc) + gr * 8);  \
            cp_async16(bBase + so, Bt + (size_t)(n0 + r) * K + (kc) + gr * 8);  \
        }                                                                       \
        cp_commit();                                                            \
    } while (0)

    ISSUE_STAGE(0, 0);
    ISSUE_STAGE(1, BK64);
    ISSUE_STAGE(2, 2 * BK64);

    for (int i = 0; i < T; i++) {
        cp_wait2();
        __syncthreads();
        const __half* As = Asm + (i % 3) * STG_ELEMS;
        const __half* Bs = Bsm + (i % 3) * STG_ELEMS;
        #pragma unroll
        for (int ks = 0; ks < 4; ks++) {
            uint32_t af[4][4], bf[4][2];
            #pragma unroll
            for (int mf = 0; mf < 4; mf++) {
                const int rA = wm + mf * 16 + g;
                af[mf][0] = *reinterpret_cast<const uint32_t*>(As + swoff(rA,     2*ks)     + 2*t4);
                af[mf][1] = *reinterpret_cast<const uint32_t*>(As + swoff(rA + 8, 2*ks)     + 2*t4);
                af[mf][2] = *reinterpret_cast<const uint32_t*>(As + swoff(rA,     2*ks + 1) + 2*t4);
                af[mf][3] = *reinterpret_cast<const uint32_t*>(As + swoff(rA + 8, 2*ks + 1) + 2*t4);
            }
            #pragma unroll
            for (int nf = 0; nf < 4; nf++) {
                const int rB = wn + nf * 8 + g;
                bf[nf][0] = *reinterpret_cast<const uint32_t*>(Bs + swoff(rB, 2*ks)     + 2*t4);
                bf[nf][1] = *reinterpret_cast<const uint32_t*>(Bs + swoff(rB, 2*ks + 1) + 2*t4);
            }
            #pragma unroll
            for (int mf = 0; mf < 4; mf++)
                #pragma unroll
                for (int nf = 0; nf < 4; nf++)
                    mma_f16(acc[mf][nf], af[mf][0], af[mf][1], af[mf][2], af[mf][3],
                            bf[nf][0], bf[nf][1]);
        }
        __syncthreads();
        if (i + 3 < T) { ISSUE_STAGE(i % 3, (i + 3) * BK64); }
        else           { cp_commit(); }
    }
    #undef ISSUE_STAGE

    // epilogue
    #pragma unroll
    for (int mf = 0; mf < 4; mf++) {
        #pragma unroll
        for (int half = 0; half < 2; half++) {
            const int row = m0 + wm + mf * 16 + g + half * 8;
            const float* rrow = (MODE == 1) ? (res + (size_t)row * N) : (const float*)0;
            #pragma unroll
            for (int nf = 0; nf < 4; nf++) {
                const int c = n0 + wn + nf * 8 + 2 * t4;
                float vx = acc[mf][nf][half * 2 + 0];
                float vy = acc[mf][nf][half * 2 + 1];
                if (MODE == 0) {
                    vx *= alpha; vy *= alpha;
                    __half2 h = __floats2half2_rn(vx, vy);
                    *reinterpret_cast<__half2*>((__half*)Cout + (size_t)row * N + c) = h;
                } else if (MODE == 1) {
                    const float2 r2 = *reinterpret_cast<const float2*>(&rrow[c]);
                    vx += bias[c]     + r2.x;
                    vy += bias[c + 1] + r2.y;
                    float2 o; o.x = vx; o.y = vy;
                    *reinterpret_cast<float2*>((float*)Cout + (size_t)row * N + c) = o;
                } else {
                    vx += bias[c]; vy += bias[c + 1];
                    vx = 0.5f * vx * (1.0f + erff(vx * 0.70710678118654752f));
                    vy = 0.5f * vy * (1.0f + erff(vy * 0.70710678118654752f));
                    __half2 h = __floats2half2_rn(vx, vy);
                    *reinterpret_cast<__half2*>((__half*)Cout + (size_t)row * N + c) = h;
                }
            }
        }
    }
}

// ---------------------------------------------------------------------------
// Flash-style attention (fp32 FFMA2 math, fp16 I/O, online softmax)
// ---------------------------------------------------------------------------
#define TK 32
__global__ __launch_bounds__(128)
void attn_kernel(const __half* __restrict__ Q, const __half* __restrict__ Kt,
                 const __half* __restrict__ Vt, __half* __restrict__ Y)
{
    const int h = blockIdx.y, b = blockIdx.z;
    const int tid  = threadIdx.x;
    const int lane = tid & 31, warp = tid >> 5;
    const int qrow = blockIdx.x * 128 + tid;

    __shared__ __align__(16) float Ks[TK][DD];
    __shared__ __align__(16) float Vs[TK][DD];
    __shared__ __align__(16) float Ss[TK][128];

    const size_t head_base = ((size_t)b * NN) * CC + (size_t)h * DD;

    unsigned long long q2[32], o2[32];
    {
        const __half2* qr =
            reinterpret_cast<const __half2*>(Q + head_base + (size_t)qrow * CC);
        #pragma unroll
        for (int i = 0; i < 32; i++) {
            const float2 f = __half22float2(qr[i]);
            q2[i] = pack2(f.x, f.y);
            o2[i] = 0ULL;
        }
    }

    float mrun = -1e30f, lrun = 0.f;

    for (int kt = 0; kt < NN; kt += TK) {
        __syncthreads();
        #pragma unroll
        for (int r = warp; r < TK; r += 4) {
            const __half2* ks = reinterpret_cast<const __half2*>(Kt + head_base + (size_t)(kt + r) * CC);
            const __half2* vs = reinterpret_cast<const __half2*>(Vt + head_base + (size_t)(kt + r) * CC);
            reinterpret_cast<float2*>(&Ks[r][0])[lane] = __half22float2(ks[lane]);
            reinterpret_cast<float2*>(&Vs[r][0])[lane] = __half22float2(vs[lane]);
        }
        __syncthreads();

        float mtile = mrun;
        #pragma unroll 4
        for (int j = 0; j < TK; j++) {
            unsigned long long acc0 = 0ULL, acc1 = 0ULL;
            const ulonglong2* kr = reinterpret_cast<const ulonglong2*>(&Ks[j][0]);
            #pragma unroll
            for (int dp = 0; dp < 16; dp++) {
                const ulonglong2 kk2 = kr[dp];
                acc0 = fma2(q2[2*dp],   kk2.x, acc0);
                acc1 = fma2(q2[2*dp+1], kk2.y, acc1);
            }
            const float2 f0 = unpack2(acc0), f1 = unpack2(acc1);
            const float s = (f0.x + f0.y) + (f1.x + f1.y);
            Ss[j][tid] = s;
            mtile = fmaxf(mtile, s);
        }

        const float corr = __expf(mrun - mtile);
        lrun *= corr;
        const unsigned long long c2 = pack2(corr, corr);
        #pragma unroll
        for (int i = 0; i < 32; i++) o2[i] = mul2(o2[i], c2);

        #pragma unroll 4
        for (int j = 0; j < TK; j++) {
            const float p = __expf(Ss[j][tid] - mtile);
            lrun += p;
            const unsigned long long p2 = pack2(p, p);
            const ulonglong2* vr = reinterpret_cast<const ulonglong2*>(&Vs[j][0]);
            #pragma unroll
            for (int dp = 0; dp < 16; dp++) {
                const ulonglong2 vv = vr[dp];
                o2[2*dp]   = fma2(p2, vv.x, o2[2*dp]);
                o2[2*dp+1] = fma2(p2, vv.y, o2[2*dp+1]);
            }
        }
        mrun = mtile;
    }

    const float invl = 1.0f / lrun;
    const unsigned long long i2 = pack2(invl, invl);
    __half2* yr = reinterpret_cast<__half2*>(Y + head_base + (size_t)qrow * CC);
    #pragma unroll
    for (int dp = 0; dp < 32; dp++) {
        const float2 f = unpack2(mul2(o2[dp], i2));
        yr[dp] = __floats2half2_rn(f.x, f.y);
    }
}

// ---------------------------------------------------------------------------
// Launch
// ---------------------------------------------------------------------------
extern "C" void kernel_launch(void* const* d_in, const int* in_sizes, int n_in,
                              void* d_out, int out_size)
{
    const float* x      = (const float*)d_in[0];
    const float* Wq     = (const float*)d_in[1];
    const float* Wk     = (const float*)d_in[2];
    const float* Wv     = (const float*)d_in[3];
    const float* Wp     = (const float*)d_in[4];
    const float* bp     = (const float*)d_in[5];
    const float* W1     = (const float*)d_in[6];
    const float* b1     = (const float*)d_in[7];
    const float* W2     = (const float*)d_in[8];
    const float* b2     = (const float*)d_in[9];
    const float* gamma1 = (const float*)d_in[10];
    const float* beta1  = (const float*)d_in[11];
    const float* gamma2 = (const float*)d_in[12];
    const float* beta2  = (const float*)d_in[13];
    float* out = (float*)d_out;

    __half *xn, *q, *k, *v, *y, *xn2, *hbuf;
    float  *x1;
    __half *wqT, *wkT, *wvT, *wpT, *w1T, *w2T;
    cudaGetSymbolAddress((void**)&xn,   g_xn);
    cudaGetSymbolAddress((void**)&q,    g_q);
    cudaGetSymbolAddress((void**)&k,    g_k);
    cudaGetSymbolAddress((void**)&v,    g_v);
    cudaGetSymbolAddress((void**)&y,    g_y);
    cudaGetSymbolAddress((void**)&x1,   g_x1);
    cudaGetSymbolAddress((void**)&xn2,  g_xn2);
    cudaGetSymbolAddress((void**)&hbuf, g_h);
    cudaGetSymbolAddress((void**)&wqT,  g_wqT);
    cudaGetSymbolAddress((void**)&wkT,  g_wkT);
    cudaGetSymbolAddress((void**)&wvT,  g_wvT);
    cudaGetSymbolAddress((void**)&wpT,  g_wpT);
    cudaGetSymbolAddress((void**)&w1T,  g_w1T);
    cudaGetSymbolAddress((void**)&w2T,  g_w2T);

    static int smem_set = 0;
    if (!smem_set) {
        cudaFuncSetAttribute(hgemm<0>, cudaFuncAttributeMaxDynamicSharedMemorySize, SMEM_GEMM);
        cudaFuncSetAttribute(hgemm<1>, cudaFuncAttributeMaxDynamicSharedMemorySize, SMEM_GEMM);
        cudaFuncSetAttribute(hgemm<2>, cudaFuncAttributeMaxDynamicSharedMemorySize, SMEM_GEMM);
        smem_set = 1;
    }

    const float scale = 0.125f;  // D^-0.5, D = 64
    const dim3 tb(32, 8);
    const dim3 gC(CC / 128, MM / 128);   // (8, 32)
    const dim3 gF(FF / 128, MM / 128);   // (32, 32)

    // Launch order arranged so ncu (-s 5 -c 1) profiles launch #6 = a C-GEMM.
    transpose_h_kernel<<<dim3(CC/32, CC/32), tb>>>(Wq, wqT, CC, CC);   // 1
    transpose_h_kernel<<<dim3(CC/32, CC/32), tb>>>(Wk, wkT, CC, CC);   // 2
    transpose_h_kernel<<<dim3(CC/32, CC/32), tb>>>(Wv, wvT, CC, CC);   // 3
    ln_kernel<<<MM, 256>>>(x, gamma1, beta1, xn);                      // 4
    hgemm<0><<<gC, 256, SMEM_GEMM>>>(xn, wqT, q, MM, CC, CC, scale, nullptr, nullptr); // 5
    hgemm<0><<<gC, 256, SMEM_GEMM>>>(xn, wkT, k, MM, CC, CC, 1.0f,  nullptr, nullptr); // 6 <- profiled
    hgemm<0><<<gC, 256, SMEM_GEMM>>>(xn, wvT, v, MM, CC, CC, 1.0f,  nullptr, nullptr); // 7
    transpose_h_kernel<<<dim3(CC/32, CC/32), tb>>>(Wp, wpT, CC, CC);   // 8
    transpose_h_kernel<<<dim3(FF/32, CC/32), tb>>>(W1, w1T, CC, FF);   // 9
    transpose_h_kernel<<<dim3(CC/32, FF/32), tb>>>(W2, w2T, FF, CC);   // 10
    attn_kernel<<<dim3(NN / 128, HH, BB), 128>>>(q, k, v, y);          // 11
    hgemm<1><<<gC, 256, SMEM_GEMM>>>(y, wpT, x1, MM, CC, CC, 1.0f, bp, x);     // 12
    ln_kernel<<<MM, 256>>>(x1, gamma2, beta2, xn2);                            // 13
    hgemm<2><<<gF, 256, SMEM_GEMM>>>(xn2, w1T, hbuf, MM, FF, CC, 1.0f, b1, nullptr); // 14
    hgemm<1><<<gC, 256, SMEM_GEMM>>>(hbuf, w2T, out, MM, CC, FF, 1.0f, b2, x1);      // 15
}

// round 10
// speedup vs baseline: 6.0002x; 2.7395x over previous
#include <cuda_runtime.h>
#include <cuda_fp16.h>
#include <math.h>
#include <stdint.h>

// ---------------------------------------------------------------------------
// Problem constants
// ---------------------------------------------------------------------------
#define BB 2
#define NN 2048
#define CC 1024
#define FF 4096
#define HH 16
#define DD 64
#define MM (BB*NN)          // 4096 rows

// ---------------------------------------------------------------------------
// Scratch (device globals: allocation-free)
// ---------------------------------------------------------------------------
__device__ __half g_xn [MM*CC];
__device__ __half g_q  [MM*CC];
__device__ __half g_k  [MM*CC];
__device__ __half g_v  [MM*CC];
__device__ __half g_y  [MM*CC];
__device__ float  g_x1 [MM*CC];
__device__ __half g_xn2[MM*CC];
__device__ __half g_h  [MM*FF];
// transposed fp16 weights ([N,K], K-contiguous rows)
__device__ __half g_wqT[CC*CC];
__device__ __half g_wkT[CC*CC];
__device__ __half g_wvT[CC*CC];
__device__ __half g_wpT[CC*CC];
__device__ __half g_w1T[CC*FF];
__device__ __half g_w2T[CC*FF];

#define DI __device__ __forceinline__

// ---------------------------------------------------------------------------
// mma / cp.async / misc helpers
// ---------------------------------------------------------------------------
DI void mma_f16(float* d, uint32_t a0, uint32_t a1, uint32_t a2, uint32_t a3,
                uint32_t b0, uint32_t b1) {
    asm volatile(
        "mma.sync.aligned.m16n8k16.row.col.f32.f16.f16.f32 "
        "{%0,%1,%2,%3}, {%4,%5,%6,%7}, {%8,%9}, {%0,%1,%2,%3};"
        : "+f"(d[0]), "+f"(d[1]), "+f"(d[2]), "+f"(d[3])
        : "r"(a0), "r"(a1), "r"(a2), "r"(a3), "r"(b0), "r"(b1));
}
DI uint32_t smem_u32(const void* p) {
    uint32_t a;
    asm("{ .reg .u64 t; cvta.to.shared.u64 t, %1; cvt.u32.u64 %0, t; }"
        : "=r"(a) : "l"(p));
    return a;
}
DI void cp_async16(uint32_t smem_addr, const void* gptr) {
    asm volatile("cp.async.ca.shared.global [%0], [%1], 16;"
                 :: "r"(smem_addr), "l"(gptr));
}
DI void cp_commit() { asm volatile("cp.async.commit_group;" ::: "memory"); }
DI float ex2f(float x) {
    float y;
    asm("ex2.approx.f32 %0, %1;" : "=f"(y) : "f"(x));
    return y;
}
DI uint32_t h2u(__half2 h) { return *reinterpret_cast<uint32_t*>(&h); }

// XOR-swizzled element offset (fp16 elems) for [row][64] tiles (128B rows,
// 16B granules): granule ^= (row & 7). Conflict-free for cp.async stores,
// fragment LDS.32, and ldmatrix row fetches.
DI int swoff(int row, int gran) { return row * 64 + (((gran) ^ (row & 7)) << 3); }

// ---------------------------------------------------------------------------
// LayerNorm: one block per row, fp32 in -> fp16 out
// ---------------------------------------------------------------------------
__global__ __launch_bounds__(256)
void ln_kernel(const float* __restrict__ x, const float* __restrict__ gamma,
               const float* __restrict__ beta, __half* __restrict__ out)
{
    const int row = blockIdx.x;
    const int tid = threadIdx.x;
    const float4* xr = reinterpret_cast<const float4*>(x + (size_t)row * CC);
    float4 v = xr[tid];

    float s  = v.x + v.y + v.z + v.w;
    float sq = v.x*v.x + v.y*v.y + v.z*v.z + v.w*v.w;

    #pragma unroll
    for (int o = 16; o > 0; o >>= 1) {
        s  += __shfl_xor_sync(0xFFFFFFFFu, s,  o);
        sq += __shfl_xor_sync(0xFFFFFFFFu, sq, o);
    }
    __shared__ float sh_s[8], sh_q[8];
    __shared__ float sh_mu, sh_inv;
    const int warp = tid >> 5, lane = tid & 31;
    if (lane == 0) { sh_s[warp] = s; sh_q[warp] = sq; }
    __syncthreads();
    if (tid == 0) {
        float S = 0.f, Q = 0.f;
        #pragma unroll
        for (int i = 0; i < 8; i++) { S += sh_s[i]; Q += sh_q[i]; }
        const float mu  = S * (1.0f / CC);
        const float var = Q * (1.0f / CC) - mu * mu;
        sh_mu  = mu;
        sh_inv = rsqrtf(var + 1e-6f);
    }
    __syncthreads();
    const float mu = sh_mu, inv = sh_inv;
    const float4 g = reinterpret_cast<const float4*>(gamma)[tid];
    const float4 b = reinterpret_cast<const float4*>(beta)[tid];
    float4 o;
    o.x = (v.x - mu) * inv * g.x + b.x;
    o.y = (v.y - mu) * inv * g.y + b.y;
    o.z = (v.z - mu) * inv * g.z + b.z;
    o.w = (v.w - mu) * inv * g.w + b.w;
    __half2 h0 = __floats2half2_rn(o.x, o.y);
    __half2 h1 = __floats2half2_rn(o.z, o.w);
    uint2 st;
    st.x = h2u(h0);
    st.y = h2u(h1);
    *reinterpret_cast<uint2*>(out + (size_t)row * CC + tid * 4) = st;
}

// ---------------------------------------------------------------------------
// Weight transpose + fp32->fp16 convert: out[C x R] = (half)in[R x C]^T
// ---------------------------------------------------------------------------
__global__ __launch_bounds__(256)
void transpose_h_kernel(const float* __restrict__ in, __half* __restrict__ out,
                        int R, int C)
{
    __shared__ float t[32][33];
    const int bx = blockIdx.x * 32;
    const int by = blockIdx.y * 32;
    const int tx = threadIdx.x, ty = threadIdx.y;
    #pragma unroll
    for (int i = ty; i < 32; i += 8)
        t[i][tx] = in[(size_t)(by + i) * C + (bx + tx)];
    __syncthreads();
    #pragma unroll
    for (int i = ty; i < 32; i += 8)
        out[(size_t)(bx + i) * R + (by + tx)] = __float2half(t[tx][i]);
}

// ---------------------------------------------------------------------------
// fp16 mma.sync GEMM: C[M,N] = epi(A[M,K] @ Bt[N,K]^T), fp32 accumulate.
// 128x128 CTA tile, BK=64, 8 warps (2m x 4n), warp tile 64x32,
// m16n8k16 mma, 3-stage cp.async pipeline, XOR-swizzled smem.
// MODE 0: out(half) = alpha*acc
// MODE 1: out(float) = acc + bias[n] + res[m][n]
// MODE 2: out(half) = gelu_exact(acc + bias[n])
// ---------------------------------------------------------------------------
#define BK64 64
#define STG_ELEMS 8192          // 128*64 halfs = 16KB per stage per matrix
#define SMEM_GEMM (6 * STG_ELEMS * 2)   // 3 stages x (A+B) = 96KB

template<int MODE>
__global__ __launch_bounds__(256)
void hgemm(const __half* __restrict__ A, const __half* __restrict__ Bt,
           void* __restrict__ Cout, int M, int N, int K,
           float alpha, const float* __restrict__ bias,
           const float* __restrict__ res)
{
    extern __shared__ __align__(16) __half sm[];
    __half* Asm = sm;                      // 3 stages
    __half* Bsm = sm + 3 * STG_ELEMS;      // 3 stages

    const int tid  = threadIdx.x;
    const int wid  = tid >> 5, lane = tid & 31;
    const int m0 = blockIdx.y * 128;
    const int n0 = blockIdx.x * 128;
    const int wm = (wid >> 2) * 64;
    const int wn = (wid & 3) * 32;
    const int g  = lane >> 2;
    const int t4 = lane & 3;

    float acc[4][4][4];
    #pragma unroll
    for (int mf = 0; mf < 4; mf++)
        #pragma unroll
        for (int nf = 0; nf < 4; nf++)
            #pragma unroll
            for (int r = 0; r < 4; r++) acc[mf][nf][r] = 0.f;

    const int T = K / BK64;

    const uint32_t smA = smem_u32(Asm);
    const uint32_t smB = smem_u32(Bsm);

    #define ISSUE_STAGE(stage, kc) do {                                         \
        const uint32_t aBase = smA + (uint32_t)(stage) * STG_ELEMS * 2;         \
        const uint32_t bBase = smB + (uint32_t)(stage) * STG_ELEMS * 2;         \
        _Pragma("unroll")                                                       \
        for (int j = 0; j < 4; j++) {                                           \
            const int id = tid + j * 256;                                       \
            const int r = id >> 3, gr = id & 7;                                 \
            const int so = swoff(r, gr) * 2;                                    \
            cp_async16(aBase + so, A  + (size_t)(m0 + r) * K + (kc) + gr * 8);  \
            cp_async16(bBase + so, Bt + (size_t)(n0 + r) * K + (kc) + gr * 8);  \
        }                                                                       \
        cp_commit();                                                            \
    } while (0)

    ISSUE_STAGE(0, 0);
    ISSUE_STAGE(1, BK64);
    ISSUE_STAGE(2, 2 * BK64);

    for (int i = 0; i < T; i++) {
        asm volatile("cp.async.wait_group 2;" ::: "memory");
        __syncthreads();
        const __half* As = Asm + (i % 3) * STG_ELEMS;
        const __half* Bs = Bsm + (i % 3) * STG_ELEMS;
        #pragma unroll
        for (int ks = 0; ks < 4; ks++) {
            uint32_t af[4][4], bf[4][2];
            #pragma unroll
            for (int mf = 0; mf < 4; mf++) {
                const int rA = wm + mf * 16 + g;
                af[mf][0] = *reinterpret_cast<const uint32_t*>(As + swoff(rA,     2*ks)     + 2*t4);
                af[mf][1] = *reinterpret_cast<const uint32_t*>(As + swoff(rA + 8, 2*ks)     + 2*t4);
                af[mf][2] = *reinterpret_cast<const uint32_t*>(As + swoff(rA,     2*ks + 1) + 2*t4);
                af[mf][3] = *reinterpret_cast<const uint32_t*>(As + swoff(rA + 8, 2*ks + 1) + 2*t4);
            }
            #pragma unroll
            for (int nf = 0; nf < 4; nf++) {
                const int rB = wn + nf * 8 + g;
                bf[nf][0] = *reinterpret_cast<const uint32_t*>(Bs + swoff(rB, 2*ks)     + 2*t4);
                bf[nf][1] = *reinterpret_cast<const uint32_t*>(Bs + swoff(rB, 2*ks + 1) + 2*t4);
            }
            #pragma unroll
            for (int mf = 0; mf < 4; mf++)
                #pragma unroll
                for (int nf = 0; nf < 4; nf++)
                    mma_f16(acc[mf][nf], af[mf][0], af[mf][1], af[mf][2], af[mf][3],
                            bf[nf][0], bf[nf][1]);
        }
        __syncthreads();
        if (i + 3 < T) { ISSUE_STAGE(i % 3, (i + 3) * BK64); }
        else           { cp_commit(); }
    }
    #undef ISSUE_STAGE

    // epilogue
    #pragma unroll
    for (int mf = 0; mf < 4; mf++) {
        #pragma unroll
        for (int half = 0; half < 2; half++) {
            const int row = m0 + wm + mf * 16 + g + half * 8;
            const float* rrow = (MODE == 1) ? (res + (size_t)row * N) : (const float*)0;
            #pragma unroll
            for (int nf = 0; nf < 4; nf++) {
                const int c = n0 + wn + nf * 8 + 2 * t4;
                float vx = acc[mf][nf][half * 2 + 0];
                float vy = acc[mf][nf][half * 2 + 1];
                if (MODE == 0) {
                    vx *= alpha; vy *= alpha;
                    __half2 h = __floats2half2_rn(vx, vy);
                    *reinterpret_cast<__half2*>((__half*)Cout + (size_t)row * N + c) = h;
                } else if (MODE == 1) {
                    const float2 r2 = *reinterpret_cast<const float2*>(&rrow[c]);
                    vx += bias[c]     + r2.x;
                    vy += bias[c + 1] + r2.y;
                    float2 o; o.x = vx; o.y = vy;
                    *reinterpret_cast<float2*>((float*)Cout + (size_t)row * N + c) = o;
                } else {
                    vx += bias[c]; vy += bias[c + 1];
                    vx = 0.5f * vx * (1.0f + erff(vx * 0.70710678118654752f));
                    vy = 0.5f * vy * (1.0f + erff(vy * 0.70710678118654752f));
                    __half2 h = __floats2half2_rn(vx, vy);
                    *reinterpret_cast<__half2*>((__half*)Cout + (size_t)row * N + c) = h;
                }
            }
        }
    }
}

// ---------------------------------------------------------------------------
// Flash attention, fp16 mma.sync tensor cores, fp32 softmax/accum.
// Block: 128 q-rows x one (b,h); 8 warps, each owns 16 q-rows x full kv tile.
// KV tiles of 64 rows, 2-stage cp.async double buffer.
// Q pre-scaled by D^-0.5 * log2(e): softmax computed in base-2 (ex2.approx).
// S accum layout == P A-fragment layout (FA2 identity). V B-fragments via
// ldmatrix.x4.trans from the [kv][d] tile.
// ---------------------------------------------------------------------------
#define QTILE 128
#define KTILE 64

__global__ __launch_bounds__(256)
void fattn_kernel(const __half* __restrict__ Q, const __half* __restrict__ K,
                  const __half* __restrict__ V, __half* __restrict__ Y)
{
    __shared__ __align__(16) __half Qs[QTILE * 64];
    __shared__ __align__(16) __half Ks[2][KTILE * 64];
    __shared__ __align__(16) __half Vs[2][KTILE * 64];

    const int h = blockIdx.y, b = blockIdx.z;
    const int q0 = blockIdx.x * QTILE;
    const int tid = threadIdx.x;
    const int wid = tid >> 5, lane = tid & 31;
    const int g = lane >> 2, t4 = lane & 3;

    const size_t base = ((size_t)b * NN) * CC + (size_t)h * DD;

    const uint32_t sQ = smem_u32(Qs);
    const uint32_t sK = smem_u32(Ks);
    const uint32_t sV = smem_u32(Vs);

    // group 0: Q tile (128 rows x 64 d)
    #pragma unroll
    for (int j = 0; j < 4; j++) {
        const int id = tid + j * 256;
        const int r = id >> 3, gr = id & 7;
        cp_async16(sQ + swoff(r, gr) * 2, Q + base + (size_t)(q0 + r) * CC + gr * 8);
    }
    cp_commit();

    #define ISSUE_KV(buf, kv0) do {                                                  \
        _Pragma("unroll")                                                            \
        for (int j = 0; j < 2; j++) {                                                \
            const int id = tid + j * 256;                                            \
            const int r = id >> 3, gr = id & 7;                                      \
            const int so = swoff(r, gr) * 2;                                         \
            cp_async16(sK + (buf) * (KTILE*128) + so,                                \
                       K + base + (size_t)((kv0) + r) * CC + gr * 8);                \
            cp_async16(sV + (buf) * (KTILE*128) + so,                                \
                       V + base + (size_t)((kv0) + r) * CC + gr * 8);                \
        }                                                                            \
        cp_commit();                                                                 \
    } while (0)

    ISSUE_KV(0, 0);
    ISSUE_KV(1, KTILE);

    // Q fragments (register-resident for the whole pass)
    asm volatile("cp.async.wait_group 2;" ::: "memory");
    __syncthreads();
    uint32_t qa[4][4];
    {
        const int r = wid * 16 + g;
        #pragma unroll
        for (int ks = 0; ks < 4; ks++) {
            qa[ks][0] = *reinterpret_cast<const uint32_t*>(Qs + swoff(r,     2*ks)     + 2*t4);
            qa[ks][1] = *reinterpret_cast<const uint32_t*>(Qs + swoff(r + 8, 2*ks)     + 2*t4);
            qa[ks][2] = *reinterpret_cast<const uint32_t*>(Qs + swoff(r,     2*ks + 1) + 2*t4);
            qa[ks][3] = *reinterpret_cast<const uint32_t*>(Qs + swoff(r + 8, 2*ks + 1) + 2*t4);
        }
    }

    float o[8][4];
    #pragma unroll
    for (int nd = 0; nd < 8; nd++)
        #pragma unroll
        for (int c = 0; c < 4; c++) o[nd][c] = 0.f;
    float m0 = -1e30f, m1 = -1e30f, l0 = 0.f, l1 = 0.f;

    const int NT = NN / KTILE;   // 32
    for (int i = 0; i < NT; i++) {
        const int buf = i & 1;
        asm volatile("cp.async.wait_group 1;" ::: "memory");
        __syncthreads();

        // ---- S = Q @ K^T (base-2-scaled logits) ----
        const __half* Kb = Ks[buf];
        float s[8][4];
        #pragma unroll
        for (int nf = 0; nf < 8; nf++)
            #pragma unroll
            for (int c = 0; c < 4; c++) s[nf][c] = 0.f;
        #pragma unroll
        for (int ks = 0; ks < 4; ks++) {
            #pragma unroll
            for (int nf = 0; nf < 8; nf++) {
                const int rB = nf * 8 + g;
                const uint32_t kb0 = *reinterpret_cast<const uint32_t*>(Kb + swoff(rB, 2*ks)     + 2*t4);
                const uint32_t kb1 = *reinterpret_cast<const uint32_t*>(Kb + swoff(rB, 2*ks + 1) + 2*t4);
                mma_f16(s[nf], qa[ks][0], qa[ks][1], qa[ks][2], qa[ks][3], kb0, kb1);
            }
        }

        // ---- online softmax (rows r = wid*16+g and r+8) ----
        float mx0 = s[0][0], mx1 = s[0][2];
        #pragma unroll
        for (int nf = 0; nf < 8; nf++) {
            mx0 = fmaxf(mx0, fmaxf(s[nf][0], s[nf][1]));
            mx1 = fmaxf(mx1, fmaxf(s[nf][2], s[nf][3]));
        }
        mx0 = fmaxf(mx0, __shfl_xor_sync(0xFFFFFFFFu, mx0, 1));
        mx0 = fmaxf(mx0, __shfl_xor_sync(0xFFFFFFFFu, mx0, 2));
        mx1 = fmaxf(mx1, __shfl_xor_sync(0xFFFFFFFFu, mx1, 1));
        mx1 = fmaxf(mx1, __shfl_xor_sync(0xFFFFFFFFu, mx1, 2));
        const float mn0 = fmaxf(m0, mx0), mn1 = fmaxf(m1, mx1);
        const float c0 = ex2f(m0 - mn0), c1 = ex2f(m1 - mn1);
        m0 = mn0; m1 = mn1;

        float sum0 = 0.f, sum1 = 0.f;
        uint32_t pa[8][2];
        #pragma unroll
        for (int nf = 0; nf < 8; nf++) {
            const float p0 = ex2f(s[nf][0] - mn0);
            const float p1 = ex2f(s[nf][1] - mn0);
            const float p2 = ex2f(s[nf][2] - mn1);
            const float p3 = ex2f(s[nf][3] - mn1);
            sum0 += p0 + p1; sum1 += p2 + p3;
            pa[nf][0] = h2u(__floats2half2_rn(p0, p1));
            pa[nf][1] = h2u(__floats2half2_rn(p2, p3));
        }
        l0 = l0 * c0 + sum0;
        l1 = l1 * c1 + sum1;
        #pragma unroll
        for (int nd = 0; nd < 8; nd++) {
            o[nd][0] *= c0; o[nd][1] *= c0;
            o[nd][2] *= c1; o[nd][3] *= c1;
        }

        // ---- O += P @ V ----
        const uint32_t vb = sV + buf * (KTILE * 128);
        const int kvl = (lane & 15);
        const int grh = (lane >> 4);
        #pragma unroll
        for (int ks = 0; ks < 4; ks++) {
            #pragma unroll
            for (int ndp = 0; ndp < 4; ndp++) {
                uint32_t b0, b1, b2, b3;
                const uint32_t addr = vb + swoff(16 * ks + kvl, ndp * 2 + grh) * 2;
                asm volatile(
                    "ldmatrix.sync.aligned.m8n8.x4.trans.shared.b16 {%0,%1,%2,%3}, [%4];"
                    : "=r"(b0), "=r"(b1), "=r"(b2), "=r"(b3) : "r"(addr));
                mma_f16(o[2*ndp],     pa[2*ks][0], pa[2*ks][1], pa[2*ks+1][0], pa[2*ks+1][1], b0, b1);
                mma_f16(o[2*ndp + 1], pa[2*ks][0], pa[2*ks][1], pa[2*ks+1][0], pa[2*ks+1][1], b2, b3);
            }
        }

        __syncthreads();
        if (i + 2 < NT) { ISSUE_KV(buf, (i + 2) * KTILE); }
        else            { cp_commit(); }
    }
    #undef ISSUE_KV

    // ---- normalize + write ----
    l0 += __shfl_xor_sync(0xFFFFFFFFu, l0, 1);
    l0 += __shfl_xor_sync(0xFFFFFFFFu, l0, 2);
    l1 += __shfl_xor_sync(0xFFFFFFFFu, l1, 1);
    l1 += __shfl_xor_sync(0xFFFFFFFFu, l1, 2);
    const float i0 = 1.0f / l0, i1 = 1.0f / l1;
    const int r0 = q0 + wid * 16 + g;
    #pragma unroll
    for (int nd = 0; nd < 8; nd++) {
        const int c = nd * 8 + 2 * t4;
        const __half2 h0 = __floats2half2_rn(o[nd][0] * i0, o[nd][1] * i0);
        const __half2 h1 = __floats2half2_rn(o[nd][2] * i1, o[nd][3] * i1);
        *reinterpret_cast<__half2*>(Y + base + (size_t)r0 * CC + c)       = h0;
        *reinterpret_cast<__half2*>(Y + base + (size_t)(r0 + 8) * CC + c) = h1;
    }
}

// ---------------------------------------------------------------------------
// Launch
// ---------------------------------------------------------------------------
extern "C" void kernel_launch(void* const* d_in, const int* in_sizes, int n_in,
                              void* d_out, int out_size)
{
    const float* x      = (const float*)d_in[0];
    const float* Wq     = (const float*)d_in[1];
    const float* Wk     = (const float*)d_in[2];
    const float* Wv     = (const float*)d_in[3];
    const float* Wp     = (const float*)d_in[4];
    const float* bp     = (const float*)d_in[5];
    const float* W1     = (const float*)d_in[6];
    const float* b1     = (const float*)d_in[7];
    const float* W2     = (const float*)d_in[8];
    const float* b2     = (const float*)d_in[9];
    const float* gamma1 = (const float*)d_in[10];
    const float* beta1  = (const float*)d_in[11];
    const float* gamma2 = (const float*)d_in[12];
    const float* beta2  = (const float*)d_in[13];
    float* out = (float*)d_out;

    __half *xn, *q, *k, *v, *y, *xn2, *hbuf;
    float  *x1;
    __half *wqT, *wkT, *wvT, *wpT, *w1T, *w2T;
    cudaGetSymbolAddress((void**)&xn,   g_xn);
    cudaGetSymbolAddress((void**)&q,    g_q);
    cudaGetSymbolAddress((void**)&k,    g_k);
    cudaGetSymbolAddress((void**)&v,    g_v);
    cudaGetSymbolAddress((void**)&y,    g_y);
    cudaGetSymbolAddress((void**)&x1,   g_x1);
    cudaGetSymbolAddress((void**)&xn2,  g_xn2);
    cudaGetSymbolAddress((void**)&hbuf, g_h);
    cudaGetSymbolAddress((void**)&wqT,  g_wqT);
    cudaGetSymbolAddress((void**)&wkT,  g_wkT);
    cudaGetSymbolAddress((void**)&wvT,  g_wvT);
    cudaGetSymbolAddress((void**)&wpT,  g_wpT);
    cudaGetSymbolAddress((void**)&w1T,  g_w1T);
    cudaGetSymbolAddress((void**)&w2T,  g_w2T);

    static int smem_set = 0;
    if (!smem_set) {
        cudaFuncSetAttribute(hgemm<0>, cudaFuncAttributeMaxDynamicSharedMemorySize, SMEM_GEMM);
        cudaFuncSetAttribute(hgemm<1>, cudaFuncAttributeMaxDynamicSharedMemorySize, SMEM_GEMM);
        cudaFuncSetAttribute(hgemm<2>, cudaFuncAttributeMaxDynamicSharedMemorySize, SMEM_GEMM);
        smem_set = 1;
    }

    // D^-0.5 * log2(e): softmax logits land pre-scaled for base-2 exp
    const float scale = 0.125f * 1.4426950408889634f;
    const dim3 tb(32, 8);
    const dim3 gC(CC / 128, MM / 128);   // (8, 32)
    const dim3 gF(FF / 128, MM / 128);   // (32, 32)

    transpose_h_kernel<<<dim3(CC/32, CC/32), tb>>>(Wq, wqT, CC, CC);
    transpose_h_kernel<<<dim3(CC/32, CC/32), tb>>>(Wk, wkT, CC, CC);
    transpose_h_kernel<<<dim3(CC/32, CC/32), tb>>>(Wv, wvT, CC, CC);
    ln_kernel<<<MM, 256>>>(x, gamma1, beta1, xn);
    hgemm<0><<<gC, 256, SMEM_GEMM>>>(xn, wqT, q, MM, CC, CC, scale, nullptr, nullptr);
    hgemm<0><<<gC, 256, SMEM_GEMM>>>(xn, wkT, k, MM, CC, CC, 1.0f,  nullptr, nullptr);
    hgemm<0><<<gC, 256, SMEM_GEMM>>>(xn, wvT, v, MM, CC, CC, 1.0f,  nullptr, nullptr);
    transpose_h_kernel<<<dim3(CC/32, CC/32), tb>>>(Wp, wpT, CC, CC);
    transpose_h_kernel<<<dim3(FF/32, CC/32), tb>>>(W1, w1T, CC, FF);
    transpose_h_kernel<<<dim3(CC/32, FF/32), tb>>>(W2, w2T, FF, CC);
    fattn_kernel<<<dim3(NN / QTILE, HH, BB), 256>>>(q, k, v, y);
    hgemm<1><<<gC, 256, SMEM_GEMM>>>(y, wpT, x1, MM, CC, CC, 1.0f, bp, x);
    ln_kernel<<<MM, 256>>>(x1, gamma2, beta2, xn2);
    hgemm<2><<<gF, 256, SMEM_GEMM>>>(xn2, w1T, hbuf, MM, FF, CC, 1.0f, b1, nullptr);
    hgemm<1><<<gC, 256, SMEM_GEMM>>>(hbuf, w2T, out, MM, CC, FF, 1.0f, b2, x1);
}

// round 11
// speedup vs baseline: 6.4830x; 1.0805x over previous
#include <cuda_runtime.h>
#include <cuda_fp16.h>
#include <math.h>
#include <stdint.h>

// ---------------------------------------------------------------------------
// Problem constants
// ---------------------------------------------------------------------------
#define BB 2
#define NN 2048
#define CC 1024
#define FF 4096
#define HH 16
#define DD 64
#define MM (BB*NN)          // 4096 rows

// ---------------------------------------------------------------------------
// Scratch (device globals: allocation-free)
// ---------------------------------------------------------------------------
__device__ __half g_xn [MM*CC];
__device__ __half g_q  [MM*CC];
__device__ __half g_k  [MM*CC];
__device__ __half g_v  [MM*CC];
__device__ __half g_y  [MM*CC];
__device__ float  g_x1 [MM*CC];
__device__ __half g_xn2[MM*CC];
__device__ __half g_h  [MM*FF];
// transposed fp16 weights ([N,K], K-contiguous rows)
__device__ __half g_wqT[CC*CC];
__device__ __half g_wkT[CC*CC];
__device__ __half g_wvT[CC*CC];
__device__ __half g_wpT[CC*CC];
__device__ __half g_w1T[CC*FF];
__device__ __half g_w2T[CC*FF];

#define DI __device__ __forceinline__

// ---------------------------------------------------------------------------
// mma / cp.async / ldmatrix helpers
// ---------------------------------------------------------------------------
DI void mma_f16(float* d, uint32_t a0, uint32_t a1, uint32_t a2, uint32_t a3,
                uint32_t b0, uint32_t b1) {
    asm volatile(
        "mma.sync.aligned.m16n8k16.row.col.f32.f16.f16.f32 "
        "{%0,%1,%2,%3}, {%4,%5,%6,%7}, {%8,%9}, {%0,%1,%2,%3};"
        : "+f"(d[0]), "+f"(d[1]), "+f"(d[2]), "+f"(d[3])
        : "r"(a0), "r"(a1), "r"(a2), "r"(a3), "r"(b0), "r"(b1));
}
DI uint32_t smem_u32(const void* p) {
    uint32_t a;
    asm("{ .reg .u64 t; cvta.to.shared.u64 t, %1; cvt.u32.u64 %0, t; }"
        : "=r"(a) : "l"(p));
    return a;
}
DI void cp_async16(uint32_t smem_addr, const void* gptr) {
    asm volatile("cp.async.ca.shared.global [%0], [%1], 16;"
                 :: "r"(smem_addr), "l"(gptr));
}
DI void cp_commit() { asm volatile("cp.async.commit_group;" ::: "memory"); }
DI void ldm_x4(uint32_t& r0, uint32_t& r1, uint32_t& r2, uint32_t& r3, uint32_t addr) {
    asm volatile("ldmatrix.sync.aligned.m8n8.x4.shared.b16 {%0,%1,%2,%3}, [%4];"
                 : "=r"(r0), "=r"(r1), "=r"(r2), "=r"(r3) : "r"(addr));
}
DI float ex2f(float x) {
    float y;
    asm("ex2.approx.f32 %0, %1;" : "=f"(y) : "f"(x));
    return y;
}
DI uint32_t h2u(__half2 h) { return *reinterpret_cast<uint32_t*>(&h); }

// XOR-swizzled element offset (fp16 elems) for [row][64] tiles (128B rows,
// 16B granules): granule ^= (row & 7). Conflict-free for cp.async stores,
// ldmatrix row fetches, and scalar fragment loads.
DI int swoff(int row, int gran) { return row * 64 + (((gran) ^ (row & 7)) << 3); }

// ---------------------------------------------------------------------------
// LayerNorm: one block per row, fp32 in -> fp16 out
// ---------------------------------------------------------------------------
__global__ __launch_bounds__(256)
void ln_kernel(const float* __restrict__ x, const float* __restrict__ gamma,
               const float* __restrict__ beta, __half* __restrict__ out)
{
    const int row = blockIdx.x;
    const int tid = threadIdx.x;
    const float4* xr = reinterpret_cast<const float4*>(x + (size_t)row * CC);
    float4 v = xr[tid];

    float s  = v.x + v.y + v.z + v.w;
    float sq = v.x*v.x + v.y*v.y + v.z*v.z + v.w*v.w;

    #pragma unroll
    for (int o = 16; o > 0; o >>= 1) {
        s  += __shfl_xor_sync(0xFFFFFFFFu, s,  o);
        sq += __shfl_xor_sync(0xFFFFFFFFu, sq, o);
    }
    __shared__ float sh_s[8], sh_q[8];
    __shared__ float sh_mu, sh_inv;
    const int warp = tid >> 5, lane = tid & 31;
    if (lane == 0) { sh_s[warp] = s; sh_q[warp] = sq; }
    __syncthreads();
    if (tid == 0) {
        float S = 0.f, Q = 0.f;
        #pragma unroll
        for (int i = 0; i < 8; i++) { S += sh_s[i]; Q += sh_q[i]; }
        const float mu  = S * (1.0f / CC);
        const float var = Q * (1.0f / CC) - mu * mu;
        sh_mu  = mu;
        sh_inv = rsqrtf(var + 1e-6f);
    }
    __syncthreads();
    const float mu = sh_mu, inv = sh_inv;
    const float4 g = reinterpret_cast<const float4*>(gamma)[tid];
    const float4 b = reinterpret_cast<const float4*>(beta)[tid];
    float4 o;
    o.x = (v.x - mu) * inv * g.x + b.x;
    o.y = (v.y - mu) * inv * g.y + b.y;
    o.z = (v.z - mu) * inv * g.z + b.z;
    o.w = (v.w - mu) * inv * g.w + b.w;
    __half2 h0 = __floats2half2_rn(o.x, o.y);
    __half2 h1 = __floats2half2_rn(o.z, o.w);
    uint2 st;
    st.x = h2u(h0);
    st.y = h2u(h1);
    *reinterpret_cast<uint2*>(out + (size_t)row * CC + tid * 4) = st;
}

// ---------------------------------------------------------------------------
// Weight transpose + fp32->fp16 convert: out[C x R] = (half)in[R x C]^T
// ---------------------------------------------------------------------------
__global__ __launch_bounds__(256)
void transpose_h_kernel(const float* __restrict__ in, __half* __restrict__ out,
                        int R, int C)
{
    __shared__ float t[32][33];
    const int bx = blockIdx.x * 32;
    const int by = blockIdx.y * 32;
    const int tx = threadIdx.x, ty = threadIdx.y;
    #pragma unroll
    for (int i = ty; i < 32; i += 8)
        t[i][tx] = in[(size_t)(by + i) * C + (bx + tx)];
    __syncthreads();
    #pragma unroll
    for (int i = ty; i < 32; i += 8)
        out[(size_t)(bx + i) * R + (by + tx)] = __float2half(t[tx][i]);
}

// ---------------------------------------------------------------------------
// fp16 mma.sync GEMM: C[M,N] = epi(A[M,K] @ Bt[N,K]^T), fp32 accumulate.
// 128x128 CTA tile, BK=64, 8 warps (2m x 4n), warp tile 64x32,
// m16n8k16 mma, 4-stage cp.async pipeline (prefetch distance 3, ONE barrier
// per k-chunk), ldmatrix.x4 fragment loads, XOR-swizzled smem.
// MODE 0: out(half) = alpha*acc
// MODE 1: out(float) = acc + bias[n] + res[m][n]
// MODE 2: out(half) = gelu_exact(acc + bias[n])
// ---------------------------------------------------------------------------
#define BK64 64
#define STG_BYTES 16384                 // 128 rows x 64 halfs x 2B
#define NSTG 4
#define SMEM_GEMM (NSTG * STG_BYTES * 2)   // 128KB

template<int MODE>
__global__ __launch_bounds__(256)
void hgemm(const __half* __restrict__ A, const __half* __restrict__ Bt,
           void* __restrict__ Cout, int M, int N, int K,
           float alpha, const float* __restrict__ bias,
           const float* __restrict__ res)
{
    extern __shared__ __align__(16) __half sm[];
    const uint32_t smA = smem_u32(sm);
    const uint32_t smB = smA + NSTG * STG_BYTES;

    const int tid  = threadIdx.x;
    const int wid  = tid >> 5, lane = tid & 31;
    const int m0 = blockIdx.y * 128;
    const int n0 = blockIdx.x * 128;
    const int wm = (wid >> 2) * 64;
    const int wn = (wid & 3) * 32;
    const int g  = lane >> 2;
    const int t4 = lane & 3;

    float acc[4][4][4];
    #pragma unroll
    for (int mf = 0; mf < 4; mf++)
        #pragma unroll
        for (int nf = 0; nf < 4; nf++)
            #pragma unroll
            for (int r = 0; r < 4; r++) acc[mf][nf][r] = 0.f;

    const int T = K / BK64;

    #define ISSUE_STAGE(stage, kc) do {                                         \
        const uint32_t aBase = smA + (uint32_t)(stage) * STG_BYTES;             \
        const uint32_t bBase = smB + (uint32_t)(stage) * STG_BYTES;             \
        _Pragma("unroll")                                                       \
        for (int j = 0; j < 4; j++) {                                           \
            const int id = tid + j * 256;                                       \
            const int r = id >> 3, gr = id & 7;                                 \
            const int so = swoff(r, gr) * 2;                                    \
            cp_async16(aBase + so, A  + (size_t)(m0 + r) * K + (kc) + gr * 8);  \
            cp_async16(bBase + so, Bt + (size_t)(n0 + r) * K + (kc) + gr * 8);  \
        }                                                                       \
        cp_commit();                                                            \
    } while (0)

    ISSUE_STAGE(0, 0);
    ISSUE_STAGE(1, BK64);
    ISSUE_STAGE(2, 2 * BK64);

    // ldmatrix lane roles
    const int aRow  = (lane & 7) + ((lane >> 3) & 1) * 8;   // + mf*16 + wm
    const int aGran = (lane >> 4);                           // + 2*ks
    const int bRow  = (lane & 7) + (lane >> 4) * 8;          // + nf2*16 + wn
    const int bGran = ((lane >> 3) & 1);                     // + 2*ks

    for (int i = 0; i < T; i++) {
        asm volatile("cp.async.wait_group 2;" ::: "memory");
        __syncthreads();
        if (i + 3 < T) { ISSUE_STAGE((i + 3) & 3, (i + 3) * BK64); }
        else           { cp_commit(); }

        const uint32_t As = smA + (uint32_t)(i & 3) * STG_BYTES;
        const uint32_t Bs = smB + (uint32_t)(i & 3) * STG_BYTES;
        #pragma unroll
        for (int ks = 0; ks < 4; ks++) {
            uint32_t af[4][4], bf[4][2];
            #pragma unroll
            for (int mf = 0; mf < 4; mf++) {
                const int row = wm + mf * 16 + aRow;
                ldm_x4(af[mf][0], af[mf][1], af[mf][2], af[mf][3],
                       As + swoff(row, 2 * ks + aGran) * 2);
            }
            #pragma unroll
            for (int nf2 = 0; nf2 < 2; nf2++) {
                const int row = wn + nf2 * 16 + bRow;
                ldm_x4(bf[2*nf2][0], bf[2*nf2][1], bf[2*nf2+1][0], bf[2*nf2+1][1],
                       Bs + swoff(row, 2 * ks + bGran) * 2);
            }
            #pragma unroll
            for (int mf = 0; mf < 4; mf++)
                #pragma unroll
                for (int nf = 0; nf < 4; nf++)
                    mma_f16(acc[mf][nf], af[mf][0], af[mf][1], af[mf][2], af[mf][3],
                            bf[nf][0], bf[nf][1]);
        }
    }
    #undef ISSUE_STAGE

    // epilogue
    #pragma unroll
    for (int mf = 0; mf < 4; mf++) {
        #pragma unroll
        for (int half = 0; half < 2; half++) {
            const int row = m0 + wm + mf * 16 + g + half * 8;
            const float* rrow = (MODE == 1) ? (res + (size_t)row * N) : (const float*)0;
            #pragma unroll
            for (int nf = 0; nf < 4; nf++) {
                const int c = n0 + wn + nf * 8 + 2 * t4;
                float vx = acc[mf][nf][half * 2 + 0];
                float vy = acc[mf][nf][half * 2 + 1];
                if (MODE == 0) {
                    vx *= alpha; vy *= alpha;
                    __half2 h = __floats2half2_rn(vx, vy);
                    *reinterpret_cast<__half2*>((__half*)Cout + (size_t)row * N + c) = h;
                } else if (MODE == 1) {
                    const float2 r2 = *reinterpret_cast<const float2*>(&rrow[c]);
                    vx += bias[c]     + r2.x;
                    vy += bias[c + 1] + r2.y;
                    float2 o; o.x = vx; o.y = vy;
                    *reinterpret_cast<float2*>((float*)Cout + (size_t)row * N + c) = o;
                } else {
                    vx += bias[c]; vy += bias[c + 1];
                    vx = 0.5f * vx * (1.0f + erff(vx * 0.70710678118654752f));
                    vy = 0.5f * vy * (1.0f + erff(vy * 0.70710678118654752f));
                    __half2 h = __floats2half2_rn(vx, vy);
                    *reinterpret_cast<__half2*>((__half*)Cout + (size_t)row * N + c) = h;
                }
            }
        }
    }
}

// ---------------------------------------------------------------------------
// Flash attention, fp16 mma.sync, fp32 softmax/accum.
// Block: 128 q-rows x one (b,h); 8 warps, each owns 16 q-rows.
// KV tiles of 64 rows, 3-buffer cp.async pipeline (distance 2, ONE barrier
// per tile). K fragments via ldmatrix.x4; V via ldmatrix.x4.trans.
// Q pre-scaled by D^-0.5 * log2(e): base-2 softmax (ex2.approx).
// ---------------------------------------------------------------------------
#define QTILE 128
#define KTILE 64
#define KVSTG_BYTES (KTILE * 64 * 2)         // 8KB... (64 rows x 64 halfs x 2B) = 8192? -> 8KB
// NOTE: KTILE*64 halfs = 4096 halfs = 8KB per matrix per stage
#define SMEM_ATTN (QTILE*64*2 + 6 * KVSTG_BYTES)   // 16KB + 48KB = 64KB

__global__ __launch_bounds__(256)
void fattn_kernel(const __half* __restrict__ Q, const __half* __restrict__ K,
                  const __half* __restrict__ V, __half* __restrict__ Y)
{
    extern __shared__ __align__(16) __half smattn[];
    const uint32_t sQ = smem_u32(smattn);
    const uint32_t sK = sQ + QTILE * 64 * 2;
    const uint32_t sV = sK + 3 * KVSTG_BYTES;

    const int h = blockIdx.y, b = blockIdx.z;
    const int q0 = blockIdx.x * QTILE;
    const int tid = threadIdx.x;
    const int wid = tid >> 5, lane = tid & 31;
    const int g = lane >> 2, t4 = lane & 3;

    const size_t base = ((size_t)b * NN) * CC + (size_t)h * DD;

    // group 1: Q tile (128 rows x 64 d)
    #pragma unroll
    for (int j = 0; j < 4; j++) {
        const int id = tid + j * 256;
        const int r = id >> 3, gr = id & 7;
        cp_async16(sQ + swoff(r, gr) * 2, Q + base + (size_t)(q0 + r) * CC + gr * 8);
    }
    cp_commit();

    #define ISSUE_KV(buf, kv0) do {                                                  \
        _Pragma("unroll")                                                            \
        for (int j = 0; j < 2; j++) {                                                \
            const int id = tid + j * 256;                                            \
            const int r = id >> 3, gr = id & 7;                                      \
            const int so = swoff(r, gr) * 2;                                         \
            cp_async16(sK + (buf) * KVSTG_BYTES + so,                                \
                       K + base + (size_t)((kv0) + r) * CC + gr * 8);                \
            cp_async16(sV + (buf) * KVSTG_BYTES + so,                                \
                       V + base + (size_t)((kv0) + r) * CC + gr * 8);                \
        }                                                                            \
        cp_commit();                                                                 \
    } while (0)

    ISSUE_KV(0, 0);
    ISSUE_KV(1, KTILE);

    // Q fragments (register-resident for the whole pass)
    asm volatile("cp.async.wait_group 2;" ::: "memory");
    __syncthreads();
    const int aRow  = (lane & 7) + ((lane >> 3) & 1) * 8;
    const int aGran = (lane >> 4);
    const int bRow  = (lane & 7) + (lane >> 4) * 8;
    const int bGran = ((lane >> 3) & 1);
    uint32_t qa[4][4];
    {
        const int r = wid * 16 + aRow;
        #pragma unroll
        for (int ks = 0; ks < 4; ks++)
            ldm_x4(qa[ks][0], qa[ks][1], qa[ks][2], qa[ks][3],
                   sQ + swoff(r, 2 * ks + aGran) * 2);
    }

    float o[8][4];
    #pragma unroll
    for (int nd = 0; nd < 8; nd++)
        #pragma unroll
        for (int c = 0; c < 4; c++) o[nd][c] = 0.f;
    float m0 = -1e30f, m1 = -1e30f, l0 = 0.f, l1 = 0.f;

    const int NT = NN / KTILE;   // 32
    int buf = 0;
    for (int i = 0; i < NT; i++) {
        asm volatile("cp.async.wait_group 1;" ::: "memory");
        __syncthreads();
        if (i + 2 < NT) {
            const int nb = (buf + 2 >= 3) ? (buf - 1) : (buf + 2);
            ISSUE_KV(nb, (i + 2) * KTILE);
        } else {
            cp_commit();
        }

        // ---- S = Q @ K^T ----
        const uint32_t Kb = sK + buf * KVSTG_BYTES;
        float s[8][4];
        #pragma unroll
        for (int nf = 0; nf < 8; nf++)
            #pragma unroll
            for (int c = 0; c < 4; c++) s[nf][c] = 0.f;
        #pragma unroll
        for (int ks = 0; ks < 4; ks++) {
            uint32_t kb[8][2];
            #pragma unroll
            for (int nf2 = 0; nf2 < 4; nf2++) {
                const int row = nf2 * 16 + bRow;
                ldm_x4(kb[2*nf2][0], kb[2*nf2][1], kb[2*nf2+1][0], kb[2*nf2+1][1],
                       Kb + swoff(row, 2 * ks + bGran) * 2);
            }
            #pragma unroll
            for (int nf = 0; nf < 8; nf++)
                mma_f16(s[nf], qa[ks][0], qa[ks][1], qa[ks][2], qa[ks][3],
                        kb[nf][0], kb[nf][1]);
        }

        // ---- online softmax (rows r = wid*16+g and r+8) ----
        float mx0 = s[0][0], mx1 = s[0][2];
        #pragma unroll
        for (int nf = 0; nf < 8; nf++) {
            mx0 = fmaxf(mx0, fmaxf(s[nf][0], s[nf][1]));
            mx1 = fmaxf(mx1, fmaxf(s[nf][2], s[nf][3]));
        }
        mx0 = fmaxf(mx0, __shfl_xor_sync(0xFFFFFFFFu, mx0, 1));
        mx0 = fmaxf(mx0, __shfl_xor_sync(0xFFFFFFFFu, mx0, 2));
        mx1 = fmaxf(mx1, __shfl_xor_sync(0xFFFFFFFFu, mx1, 1));
        mx1 = fmaxf(mx1, __shfl_xor_sync(0xFFFFFFFFu, mx1, 2));
        const float mn0 = fmaxf(m0, mx0), mn1 = fmaxf(m1, mx1);
        const float c0 = ex2f(m0 - mn0), c1 = ex2f(m1 - mn1);
        m0 = mn0; m1 = mn1;

        float sum0 = 0.f, sum1 = 0.f;
        uint32_t pa[8][2];
        #pragma unroll
        for (int nf = 0; nf < 8; nf++) {
            const float p0 = ex2f(s[nf][0] - mn0);
            const float p1 = ex2f(s[nf][1] - mn0);
            const float p2 = ex2f(s[nf][2] - mn1);
            const float p3 = ex2f(s[nf][3] - mn1);
            sum0 += p0 + p1; sum1 += p2 + p3;
            pa[nf][0] = h2u(__floats2half2_rn(p0, p1));
            pa[nf][1] = h2u(__floats2half2_rn(p2, p3));
        }
        l0 = l0 * c0 + sum0;
        l1 = l1 * c1 + sum1;
        #pragma unroll
        for (int nd = 0; nd < 8; nd++) {
            o[nd][0] *= c0; o[nd][1] *= c0;
            o[nd][2] *= c1; o[nd][3] *= c1;
        }

        // ---- O += P @ V ----
        const uint32_t vb = sV + buf * KVSTG_BYTES;
        const int kvl = (lane & 15);
        const int grh = (lane >> 4);
        #pragma unroll
        for (int ks = 0; ks < 4; ks++) {
            #pragma unroll
            for (int ndp = 0; ndp < 4; ndp++) {
                uint32_t b0, b1, b2, b3;
                const uint32_t addr = vb + swoff(16 * ks + kvl, ndp * 2 + grh) * 2;
                asm volatile(
                    "ldmatrix.sync.aligned.m8n8.x4.trans.shared.b16 {%0,%1,%2,%3}, [%4];"
                    : "=r"(b0), "=r"(b1), "=r"(b2), "=r"(b3) : "r"(addr));
                mma_f16(o[2*ndp],     pa[2*ks][0], pa[2*ks][1], pa[2*ks+1][0], pa[2*ks+1][1], b0, b1);
                mma_f16(o[2*ndp + 1], pa[2*ks][0], pa[2*ks][1], pa[2*ks+1][0], pa[2*ks+1][1], b2, b3);
            }
        }
        buf = (buf + 1 >= 3) ? 0 : (buf + 1);
    }
    #undef ISSUE_KV

    // ---- normalize + write ----
    l0 += __shfl_xor_sync(0xFFFFFFFFu, l0, 1);
    l0 += __shfl_xor_sync(0xFFFFFFFFu, l0, 2);
    l1 += __shfl_xor_sync(0xFFFFFFFFu, l1, 1);
    l1 += __shfl_xor_sync(0xFFFFFFFFu, l1, 2);
    const float i0 = 1.0f / l0, i1 = 1.0f / l1;
    const int r0 = q0 + wid * 16 + g;
    #pragma unroll
    for (int nd = 0; nd < 8; nd++) {
        const int c = nd * 8 + 2 * t4;
        const __half2 h0 = __floats2half2_rn(o[nd][0] * i0, o[nd][1] * i0);
        const __half2 h1 = __floats2half2_rn(o[nd][2] * i1, o[nd][3] * i1);
        *reinterpret_cast<__half2*>(Y + base + (size_t)r0 * CC + c)       = h0;
        *reinterpret_cast<__half2*>(Y + base + (size_t)(r0 + 8) * CC + c) = h1;
    }
}

// ---------------------------------------------------------------------------
// Launch
// ---------------------------------------------------------------------------
extern "C" void kernel_launch(void* const* d_in, const int* in_sizes, int n_in,
                              void* d_out, int out_size)
{
    const float* x      = (const float*)d_in[0];
    const float* Wq     = (const float*)d_in[1];
    const float* Wk     = (const float*)d_in[2];
    const float* Wv     = (const float*)d_in[3];
    const float* Wp     = (const float*)d_in[4];
    const float* bp     = (const float*)d_in[5];
    const float* W1     = (const float*)d_in[6];
    const float* b1     = (const float*)d_in[7];
    const float* W2     = (const float*)d_in[8];
    const float* b2     = (const float*)d_in[9];
    const float* gamma1 = (const float*)d_in[10];
    const float* beta1  = (const float*)d_in[11];
    const float* gamma2 = (const float*)d_in[12];
    const float* beta2  = (const float*)d_in[13];
    float* out = (float*)d_out;

    __half *xn, *q, *k, *v, *y, *xn2, *hbuf;
    float  *x1;
    __half *wqT, *wkT, *wvT, *wpT, *w1T, *w2T;
    cudaGetSymbolAddress((void**)&xn,   g_xn);
    cudaGetSymbolAddress((void**)&q,    g_q);
    cudaGetSymbolAddress((void**)&k,    g_k);
    cudaGetSymbolAddress((void**)&v,    g_v);
    cudaGetSymbolAddress((void**)&y,    g_y);
    cudaGetSymbolAddress((void**)&x1,   g_x1);
    cudaGetSymbolAddress((void**)&xn2,  g_xn2);
    cudaGetSymbolAddress((void**)&hbuf, g_h);
    cudaGetSymbolAddress((void**)&wqT,  g_wqT);
    cudaGetSymbolAddress((void**)&wkT,  g_wkT);
    cudaGetSymbolAddress((void**)&wvT,  g_wvT);
    cudaGetSymbolAddress((void**)&wpT,  g_wpT);
    cudaGetSymbolAddress((void**)&w1T,  g_w1T);
    cudaGetSymbolAddress((void**)&w2T,  g_w2T);

    static int smem_set = 0;
    if (!smem_set) {
        cudaFuncSetAttribute(hgemm<0>, cudaFuncAttributeMaxDynamicSharedMemorySize, SMEM_GEMM);
        cudaFuncSetAttribute(hgemm<1>, cudaFuncAttributeMaxDynamicSharedMemorySize, SMEM_GEMM);
        cudaFuncSetAttribute(hgemm<2>, cudaFuncAttributeMaxDynamicSharedMemorySize, SMEM_GEMM);
        cudaFuncSetAttribute(fattn_kernel, cudaFuncAttributeMaxDynamicSharedMemorySize, SMEM_ATTN);
        smem_set = 1;
    }

    // D^-0.5 * log2(e): softmax logits land pre-scaled for base-2 exp
    const float scale = 0.125f * 1.4426950408889634f;
    const dim3 tb(32, 8);
    const dim3 gC(CC / 128, MM / 128);   // (8, 32)
    const dim3 gF(FF / 128, MM / 128);   // (32, 32)

    // Order chosen so the ncu-profiled slot (#4) is an hgemm.
    transpose_h_kernel<<<dim3(CC/32, CC/32), tb>>>(Wq, wqT, CC, CC);                    // 1
    ln_kernel<<<MM, 256>>>(x, gamma1, beta1, xn);                                       // 2
    transpose_h_kernel<<<dim3(CC/32, CC/32), tb>>>(Wk, wkT, CC, CC);                    // 3
    hgemm<0><<<gC, 256, SMEM_GEMM>>>(xn, wqT, q, MM, CC, CC, scale, nullptr, nullptr);  // 4 <- profiled
    transpose_h_kernel<<<dim3(CC/32, CC/32), tb>>>(Wv, wvT, CC, CC);                    // 5
    hgemm<0><<<gC, 256, SMEM_GEMM>>>(xn, wkT, k, MM, CC, CC, 1.0f,  nullptr, nullptr);  // 6
    hgemm<0><<<gC, 256, SMEM_GEMM>>>(xn, wvT, v, MM, CC, CC, 1.0f,  nullptr, nullptr);  // 7
    transpose_h_kernel<<<dim3(CC/32, CC/32), tb>>>(Wp, wpT, CC, CC);                    // 8
    transpose_h_kernel<<<dim3(FF/32, CC/32), tb>>>(W1, w1T, CC, FF);                    // 9
    transpose_h_kernel<<<dim3(CC/32, FF/32), tb>>>(W2, w2T, FF, CC);                    // 10
    fattn_kernel<<<dim3(NN / QTILE, HH, BB), 256, SMEM_ATTN>>>(q, k, v, y);             // 11
    hgemm<1><<<gC, 256, SMEM_GEMM>>>(y, wpT, x1, MM, CC, CC, 1.0f, bp, x);              // 12
    ln_kernel<<<MM, 256>>>(x1, gamma2, beta2, xn2);                                     // 13
    hgemm<2><<<gF, 256, SMEM_GEMM>>>(xn2, w1T, hbuf, MM, FF, CC, 1.0f, b1, nullptr);    // 14
    hgemm<1><<<gC, 256, SMEM_GEMM>>>(hbuf, w2T, out, MM, CC, FF, 1.0f, b2, x1);         // 15
}

// round 12
// speedup vs baseline: 7.0732x; 1.0910x over previous
#include <cuda_runtime.h>
#include <cuda_fp16.h>
#include <math.h>
#include <stdint.h>

// ---------------------------------------------------------------------------
// Problem constants
// ---------------------------------------------------------------------------
#define BB 2
#define NN 2048
#define CC 1024
#define FF 4096
#define HH 16
#define DD 64
#define MM (BB*NN)          // 4096 rows

// ---------------------------------------------------------------------------
// Scratch (device globals: allocation-free)
// ---------------------------------------------------------------------------
__device__ __half g_xn [MM*CC];
__device__ __half g_q  [MM*CC];
__device__ __half g_k  [MM*CC];
__device__ __half g_v  [MM*CC];
__device__ __half g_y  [MM*CC];
__device__ float  g_x1 [MM*CC];
__device__ __half g_xn2[MM*CC];
__device__ __half g_h  [MM*FF];
// transposed fp16 weights ([N,K], K-contiguous rows)
__device__ __half g_wqkvT[3*CC*CC];     // q rows 0..1023, k 1024..2047, v 2048..3071
__device__ __half g_wpT[CC*CC];
__device__ __half g_w1T[CC*FF];
__device__ __half g_w2T[CC*FF];

#define DI __device__ __forceinline__

// ---------------------------------------------------------------------------
// mma / cp.async / ldmatrix helpers
// ---------------------------------------------------------------------------
DI void mma_f16(float* d, uint32_t a0, uint32_t a1, uint32_t a2, uint32_t a3,
                uint32_t b0, uint32_t b1) {
    asm volatile(
        "mma.sync.aligned.m16n8k16.row.col.f32.f16.f16.f32 "
        "{%0,%1,%2,%3}, {%4,%5,%6,%7}, {%8,%9}, {%0,%1,%2,%3};"
        : "+f"(d[0]), "+f"(d[1]), "+f"(d[2]), "+f"(d[3])
        : "r"(a0), "r"(a1), "r"(a2), "r"(a3), "r"(b0), "r"(b1));
}
DI uint32_t smem_u32(const void* p) {
    uint32_t a;
    asm("{ .reg .u64 t; cvta.to.shared.u64 t, %1; cvt.u32.u64 %0, t; }"
        : "=r"(a) : "l"(p));
    return a;
}
DI void cp_async16(uint32_t smem_addr, const void* gptr) {
    asm volatile("cp.async.ca.shared.global [%0], [%1], 16;"
                 :: "r"(smem_addr), "l"(gptr));
}
DI void cp_commit() { asm volatile("cp.async.commit_group;" ::: "memory"); }
DI void ldm_x4(uint32_t& r0, uint32_t& r1, uint32_t& r2, uint32_t& r3, uint32_t addr) {
    asm volatile("ldmatrix.sync.aligned.m8n8.x4.shared.b16 {%0,%1,%2,%3}, [%4];"
                 : "=r"(r0), "=r"(r1), "=r"(r2), "=r"(r3) : "r"(addr));
}
DI float ex2f(float x) {
    float y;
    asm("ex2.approx.f32 %0, %1;" : "=f"(y) : "f"(x));
    return y;
}
DI uint32_t h2u(__half2 h) { return *reinterpret_cast<uint32_t*>(&h); }

// XOR-swizzled element offset (fp16 elems) for [row][64] tiles (128B rows,
// 16B granules): granule ^= (row & 7).
DI int swoff(int row, int gran) { return row * 64 + (((gran) ^ (row & 7)) << 3); }

// ---------------------------------------------------------------------------
// LayerNorm: one block per row, fp32 in -> fp16 out
// ---------------------------------------------------------------------------
__global__ __launch_bounds__(256)
void ln_kernel(const float* __restrict__ x, const float* __restrict__ gamma,
               const float* __restrict__ beta, __half* __restrict__ out)
{
    const int row = blockIdx.x;
    const int tid = threadIdx.x;
    const float4* xr = reinterpret_cast<const float4*>(x + (size_t)row * CC);
    float4 v = xr[tid];

    float s  = v.x + v.y + v.z + v.w;
    float sq = v.x*v.x + v.y*v.y + v.z*v.z + v.w*v.w;

    #pragma unroll
    for (int o = 16; o > 0; o >>= 1) {
        s  += __shfl_xor_sync(0xFFFFFFFFu, s,  o);
        sq += __shfl_xor_sync(0xFFFFFFFFu, sq, o);
    }
    __shared__ float sh_s[8], sh_q[8];
    __shared__ float sh_mu, sh_inv;
    const int warp = tid >> 5, lane = tid & 31;
    if (lane == 0) { sh_s[warp] = s; sh_q[warp] = sq; }
    __syncthreads();
    if (tid == 0) {
        float S = 0.f, Q = 0.f;
        #pragma unroll
        for (int i = 0; i < 8; i++) { S += sh_s[i]; Q += sh_q[i]; }
        const float mu  = S * (1.0f / CC);
        const float var = Q * (1.0f / CC) - mu * mu;
        sh_mu  = mu;
        sh_inv = rsqrtf(var + 1e-6f);
    }
    __syncthreads();
    const float mu = sh_mu, inv = sh_inv;
    const float4 g = reinterpret_cast<const float4*>(gamma)[tid];
    const float4 b = reinterpret_cast<const float4*>(beta)[tid];
    float4 o;
    o.x = (v.x - mu) * inv * g.x + b.x;
    o.y = (v.y - mu) * inv * g.y + b.y;
    o.z = (v.z - mu) * inv * g.z + b.z;
    o.w = (v.w - mu) * inv * g.w + b.w;
    __half2 h0 = __floats2half2_rn(o.x, o.y);
    __half2 h1 = __floats2half2_rn(o.z, o.w);
    uint2 st;
    st.x = h2u(h0);
    st.y = h2u(h1);
    *reinterpret_cast<uint2*>(out + (size_t)row * CC + tid * 4) = st;
}

// ---------------------------------------------------------------------------
// Weight transpose + fp32->fp16 convert: out[C x R] = (half)in[R x C]^T
// ---------------------------------------------------------------------------
__global__ __launch_bounds__(256)
void transpose_h_kernel(const float* __restrict__ in, __half* __restrict__ out,
                        int R, int C)
{
    __shared__ float t[32][33];
    const int bx = blockIdx.x * 32;
    const int by = blockIdx.y * 32;
    const int tx = threadIdx.x, ty = threadIdx.y;
    #pragma unroll
    for (int i = ty; i < 32; i += 8)
        t[i][tx] = in[(size_t)(by + i) * C + (bx + tx)];
    __syncthreads();
    #pragma unroll
    for (int i = ty; i < 32; i += 8)
        out[(size_t)(bx + i) * R + (by + tx)] = __float2half(t[tx][i]);
}

// Merged QKV weight transpose: z in {0,1,2} selects Wq/Wk/Wv
__global__ __launch_bounds__(256)
void transpose_qkv_kernel(const float* __restrict__ Wq, const float* __restrict__ Wk,
                          const float* __restrict__ Wv, __half* __restrict__ out)
{
    __shared__ float t[32][33];
    const float* in = (blockIdx.z == 0) ? Wq : (blockIdx.z == 1) ? Wk : Wv;
    __half* o = out + (size_t)blockIdx.z * CC * CC;
    const int bx = blockIdx.x * 32;
    const int by = blockIdx.y * 32;
    const int tx = threadIdx.x, ty = threadIdx.y;
    #pragma unroll
    for (int i = ty; i < 32; i += 8)
        t[i][tx] = in[(size_t)(by + i) * CC + (bx + tx)];
    __syncthreads();
    #pragma unroll
    for (int i = ty; i < 32; i += 8)
        o[(size_t)(bx + i) * CC + (by + tx)] = __float2half(t[tx][i]);
}

// ---------------------------------------------------------------------------
// fp16 mma.sync GEMM: C[M,N] = epi(A[M,K] @ Bt[N,K]^T), fp32 accumulate.
// 128x128 CTA tile, BK=64, 8 warps (2m x 4n), warp tile 64x32, m16n8k16.
// 3-stage cp.async pipeline (distance 2, wait_group 1, ONE barrier/chunk),
// ldmatrix.x4 fragment loads, XOR-swizzled smem. 96KB smem -> 2 CTAs/SM.
// MODE 0: out(half) = alpha*acc
// MODE 1: out(float) = acc + bias[n] + res[m][n]
// MODE 2: out(half) = gelu_exact(acc + bias[n])
// MODE 3: fused QKV: Bt is [3C,C]; block col selects q/k/v dst, alpha on q only
// ---------------------------------------------------------------------------
#define BK64 64
#define STG_BYTES 16384                 // 128 rows x 64 halfs x 2B
#define NSTG 3
#define SMEM_GEMM (NSTG * STG_BYTES * 2)   // 96KB

template<int MODE>
__global__ __launch_bounds__(256, 2)
void hgemm(const __half* __restrict__ A, const __half* __restrict__ Bt,
           void* __restrict__ Cout, int M, int N, int K,
           float alpha, const float* __restrict__ bias,
           const float* __restrict__ res,
           __half* __restrict__ kOut = nullptr, __half* __restrict__ vOut = nullptr)
{
    extern __shared__ __align__(16) __half sm[];
    const uint32_t smA = smem_u32(sm);
    const uint32_t smB = smA + NSTG * STG_BYTES;

    const int tid  = threadIdx.x;
    const int wid  = tid >> 5, lane = tid & 31;
    const int m0 = blockIdx.y * 128;
    const int nB0 = blockIdx.x * 128;   // B-row block (spans 3C in MODE 3)
    const int wm = (wid >> 2) * 64;
    const int wn = (wid & 3) * 32;
    const int g  = lane >> 2;
    const int t4 = lane & 3;

    float acc[4][4][4];
    #pragma unroll
    for (int mf = 0; mf < 4; mf++)
        #pragma unroll
        for (int nf = 0; nf < 4; nf++)
            #pragma unroll
            for (int r = 0; r < 4; r++) acc[mf][nf][r] = 0.f;

    const int T = K / BK64;

    #define ISSUE_STAGE(stage, kc) do {                                         \
        const uint32_t aBase = smA + (uint32_t)(stage) * STG_BYTES;             \
        const uint32_t bBase = smB + (uint32_t)(stage) * STG_BYTES;             \
        _Pragma("unroll")                                                       \
        for (int j = 0; j < 4; j++) {                                           \
            const int id = tid + j * 256;                                       \
            const int r = id >> 3, gr = id & 7;                                 \
            const int so = swoff(r, gr) * 2;                                    \
            cp_async16(aBase + so, A  + (size_t)(m0 + r) * K + (kc) + gr * 8);  \
            cp_async16(bBase + so, Bt + (size_t)(nB0 + r) * K + (kc) + gr * 8); \
        }                                                                       \
        cp_commit();                                                            \
    } while (0)

    ISSUE_STAGE(0, 0);
    ISSUE_STAGE(1, BK64);

    // ldmatrix lane roles
    const int aRow  = (lane & 7) + ((lane >> 3) & 1) * 8;
    const int aGran = (lane >> 4);
    const int bRow  = (lane & 7) + (lane >> 4) * 8;
    const int bGran = ((lane >> 3) & 1);

    int stg = 0;
    for (int i = 0; i < T; i++) {
        asm volatile("cp.async.wait_group 1;" ::: "memory");
        __syncthreads();
        if (i + 2 < T) {
            const int ns = (stg + 2 >= NSTG) ? (stg + 2 - NSTG) : (stg + 2);
            ISSUE_STAGE(ns, (i + 2) * BK64);
        } else {
            cp_commit();
        }

        const uint32_t As = smA + (uint32_t)stg * STG_BYTES;
        const uint32_t Bs = smB + (uint32_t)stg * STG_BYTES;
        #pragma unroll
        for (int ks = 0; ks < 4; ks++) {
            uint32_t af[4][4], bf[4][2];
            #pragma unroll
            for (int mf = 0; mf < 4; mf++) {
                const int row = wm + mf * 16 + aRow;
                ldm_x4(af[mf][0], af[mf][1], af[mf][2], af[mf][3],
                       As + swoff(row, 2 * ks + aGran) * 2);
            }
            #pragma unroll
            for (int nf2 = 0; nf2 < 2; nf2++) {
                const int row = wn + nf2 * 16 + bRow;
                ldm_x4(bf[2*nf2][0], bf[2*nf2][1], bf[2*nf2+1][0], bf[2*nf2+1][1],
                       Bs + swoff(row, 2 * ks + bGran) * 2);
            }
            #pragma unroll
            for (int mf = 0; mf < 4; mf++)
                #pragma unroll
                for (int nf = 0; nf < 4; nf++)
                    mma_f16(acc[mf][nf], af[mf][0], af[mf][1], af[mf][2], af[mf][3],
                            bf[nf][0], bf[nf][1]);
        }
        stg = (stg + 1 >= NSTG) ? 0 : (stg + 1);
    }
    #undef ISSUE_STAGE

    // epilogue
    int n0 = nB0;
    __half* dstH = (__half*)Cout;
    float alph = alpha;
    if (MODE == 3) {
        const int which = blockIdx.x >> 3;          // 0:q 1:k 2:v (gx = 24)
        n0 = (blockIdx.x & 7) * 128;
        dstH = (which == 0) ? (__half*)Cout : (which == 1) ? kOut : vOut;
        alph = (which == 0) ? alpha : 1.0f;
    }
    #pragma unroll
    for (int mf = 0; mf < 4; mf++) {
        #pragma unroll
        for (int half = 0; half < 2; half++) {
            const int row = m0 + wm + mf * 16 + g + half * 8;
            const float* rrow = (MODE == 1) ? (res + (size_t)row * N) : (const float*)0;
            #pragma unroll
            for (int nf = 0; nf < 4; nf++) {
                const int c = n0 + wn + nf * 8 + 2 * t4;
                float vx = acc[mf][nf][half * 2 + 0];
                float vy = acc[mf][nf][half * 2 + 1];
                if (MODE == 0 || MODE == 3) {
                    vx *= alph; vy *= alph;
                    __half2 h = __floats2half2_rn(vx, vy);
                    *reinterpret_cast<__half2*>(dstH + (size_t)row * N + c) = h;
                } else if (MODE == 1) {
                    const float2 r2 = *reinterpret_cast<const float2*>(&rrow[c]);
                    vx += bias[c]     + r2.x;
                    vy += bias[c + 1] + r2.y;
                    float2 o; o.x = vx; o.y = vy;
                    *reinterpret_cast<float2*>((float*)Cout + (size_t)row * N + c) = o;
                } else {
                    vx += bias[c]; vy += bias[c + 1];
                    vx = 0.5f * vx * (1.0f + erff(vx * 0.70710678118654752f));
                    vy = 0.5f * vy * (1.0f + erff(vy * 0.70710678118654752f));
                    __half2 h = __floats2half2_rn(vx, vy);
                    *reinterpret_cast<__half2*>(dstH + (size_t)row * N + c) = h;
                }
            }
        }
    }
}

// ---------------------------------------------------------------------------
// Flash attention, fp16 mma.sync, fp32 softmax/accum. (unchanged from R11)
// ---------------------------------------------------------------------------
#define QTILE 128
#define KTILE 64
#define KVSTG_BYTES (KTILE * 64 * 2)               // 8KB per matrix per stage
#define SMEM_ATTN (QTILE*64*2 + 6 * KVSTG_BYTES)   // 64KB

__global__ __launch_bounds__(256)
void fattn_kernel(const __half* __restrict__ Q, const __half* __restrict__ K,
                  const __half* __restrict__ V, __half* __restrict__ Y)
{
    extern __shared__ __align__(16) __half smattn[];
    const uint32_t sQ = smem_u32(smattn);
    const uint32_t sK = sQ + QTILE * 64 * 2;
    const uint32_t sV = sK + 3 * KVSTG_BYTES;

    const int h = blockIdx.y, b = blockIdx.z;
    const int q0 = blockIdx.x * QTILE;
    const int tid = threadIdx.x;
    const int wid = tid >> 5, lane = tid & 31;
    const int g = lane >> 2, t4 = lane & 3;

    const size_t base = ((size_t)b * NN) * CC + (size_t)h * DD;

    #pragma unroll
    for (int j = 0; j < 4; j++) {
        const int id = tid + j * 256;
        const int r = id >> 3, gr = id & 7;
        cp_async16(sQ + swoff(r, gr) * 2, Q + base + (size_t)(q0 + r) * CC + gr * 8);
    }
    cp_commit();

    #define ISSUE_KV(buf, kv0) do {                                                  \
        _Pragma("unroll")                                                            \
        for (int j = 0; j < 2; j++) {                                                \
            const int id = tid + j * 256;                                            \
            const int r = id >> 3, gr = id & 7;                                      \
            const int so = swoff(r, gr) * 2;                                         \
            cp_async16(sK + (buf) * KVSTG_BYTES + so,                                \
                       K + base + (size_t)((kv0) + r) * CC + gr * 8);                \
            cp_async16(sV + (buf) * KVSTG_BYTES + so,                                \
                       V + base + (size_t)((kv0) + r) * CC + gr * 8);                \
        }                                                                            \
        cp_commit();                                                                 \
    } while (0)

    ISSUE_KV(0, 0);
    ISSUE_KV(1, KTILE);

    asm volatile("cp.async.wait_group 2;" ::: "memory");
    __syncthreads();
    const int aRow  = (lane & 7) + ((lane >> 3) & 1) * 8;
    const int aGran = (lane >> 4);
    const int bRow  = (lane & 7) + (lane >> 4) * 8;
    const int bGran = ((lane >> 3) & 1);
    uint32_t qa[4][4];
    {
        const int r = wid * 16 + aRow;
        #pragma unroll
        for (int ks = 0; ks < 4; ks++)
            ldm_x4(qa[ks][0], qa[ks][1], qa[ks][2], qa[ks][3],
                   sQ + swoff(r, 2 * ks + aGran) * 2);
    }

    float o[8][4];
    #pragma unroll
    for (int nd = 0; nd < 8; nd++)
        #pragma unroll
        for (int c = 0; c < 4; c++) o[nd][c] = 0.f;
    float m0 = -1e30f, m1 = -1e30f, l0 = 0.f, l1 = 0.f;

    const int NT = NN / KTILE;   // 32
    int buf = 0;
    for (int i = 0; i < NT; i++) {
        asm volatile("cp.async.wait_group 1;" ::: "memory");
        __syncthreads();
        if (i + 2 < NT) {
            const int nb = (buf + 2 >= 3) ? (buf - 1) : (buf + 2);
            ISSUE_KV(nb, (i + 2) * KTILE);
        } else {
            cp_commit();
        }

        // ---- S = Q @ K^T ----
        const uint32_t Kb = sK + buf * KVSTG_BYTES;
        float s[8][4];
        #pragma unroll
        for (int nf = 0; nf < 8; nf++)
            #pragma unroll
            for (int c = 0; c < 4; c++) s[nf][c] = 0.f;
        #pragma unroll
        for (int ks = 0; ks < 4; ks++) {
            uint32_t kb[8][2];
            #pragma unroll
            for (int nf2 = 0; nf2 < 4; nf2++) {
                const int row = nf2 * 16 + bRow;
                ldm_x4(kb[2*nf2][0], kb[2*nf2][1], kb[2*nf2+1][0], kb[2*nf2+1][1],
                       Kb + swoff(row, 2 * ks + bGran) * 2);
            }
            #pragma unroll
            for (int nf = 0; nf < 8; nf++)
                mma_f16(s[nf], qa[ks][0], qa[ks][1], qa[ks][2], qa[ks][3],
                        kb[nf][0], kb[nf][1]);
        }

        // ---- online softmax ----
        float mx0 = s[0][0], mx1 = s[0][2];
        #pragma unroll
        for (int nf = 0; nf < 8; nf++) {
            mx0 = fmaxf(mx0, fmaxf(s[nf][0], s[nf][1]));
            mx1 = fmaxf(mx1, fmaxf(s[nf][2], s[nf][3]));
        }
        mx0 = fmaxf(mx0, __shfl_xor_sync(0xFFFFFFFFu, mx0, 1));
        mx0 = fmaxf(mx0, __shfl_xor_sync(0xFFFFFFFFu, mx0, 2));
        mx1 = fmaxf(mx1, __shfl_xor_sync(0xFFFFFFFFu, mx1, 1));
        mx1 = fmaxf(mx1, __shfl_xor_sync(0xFFFFFFFFu, mx1, 2));
        const float mn0 = fmaxf(m0, mx0), mn1 = fmaxf(m1, mx1);
        const float c0 = ex2f(m0 - mn0), c1 = ex2f(m1 - mn1);
        m0 = mn0; m1 = mn1;

        float sum0 = 0.f, sum1 = 0.f;
        uint32_t pa[8][2];
        #pragma unroll
        for (int nf = 0; nf < 8; nf++) {
            const float p0 = ex2f(s[nf][0] - mn0);
            const float p1 = ex2f(s[nf][1] - mn0);
            const float p2 = ex2f(s[nf][2] - mn1);
            const float p3 = ex2f(s[nf][3] - mn1);
            sum0 += p0 + p1; sum1 += p2 + p3;
            pa[nf][0] = h2u(__floats2half2_rn(p0, p1));
            pa[nf][1] = h2u(__floats2half2_rn(p2, p3));
        }
        l0 = l0 * c0 + sum0;
        l1 = l1 * c1 + sum1;
        #pragma unroll
        for (int nd = 0; nd < 8; nd++) {
            o[nd][0] *= c0; o[nd][1] *= c0;
            o[nd][2] *= c1; o[nd][3] *= c1;
        }

        // ---- O += P @ V ----
        const uint32_t vb = sV + buf * KVSTG_BYTES;
        const int kvl = (lane & 15);
        const int grh = (lane >> 4);
        #pragma unroll
        for (int ks = 0; ks < 4; ks++) {
            #pragma unroll
            for (int ndp = 0; ndp < 4; ndp++) {
                uint32_t b0, b1, b2, b3;
                const uint32_t addr = vb + swoff(16 * ks + kvl, ndp * 2 + grh) * 2;
                asm volatile(
                    "ldmatrix.sync.aligned.m8n8.x4.trans.shared.b16 {%0,%1,%2,%3}, [%4];"
                    : "=r"(b0), "=r"(b1), "=r"(b2), "=r"(b3) : "r"(addr));
                mma_f16(o[2*ndp],     pa[2*ks][0], pa[2*ks][1], pa[2*ks+1][0], pa[2*ks+1][1], b0, b1);
                mma_f16(o[2*ndp + 1], pa[2*ks][0], pa[2*ks][1], pa[2*ks+1][0], pa[2*ks+1][1], b2, b3);
            }
        }
        buf = (buf + 1 >= 3) ? 0 : (buf + 1);
    }
    #undef ISSUE_KV

    // ---- normalize + write ----
    l0 += __shfl_xor_sync(0xFFFFFFFFu, l0, 1);
    l0 += __shfl_xor_sync(0xFFFFFFFFu, l0, 2);
    l1 += __shfl_xor_sync(0xFFFFFFFFu, l1, 1);
    l1 += __shfl_xor_sync(0xFFFFFFFFu, l1, 2);
    const float i0 = 1.0f / l0, i1 = 1.0f / l1;
    const int r0 = q0 + wid * 16 + g;
    #pragma unroll
    for (int nd = 0; nd < 8; nd++) {
        const int c = nd * 8 + 2 * t4;
        const __half2 h0 = __floats2half2_rn(o[nd][0] * i0, o[nd][1] * i0);
        const __half2 h1 = __floats2half2_rn(o[nd][2] * i1, o[nd][3] * i1);
        *reinterpret_cast<__half2*>(Y + base + (size_t)r0 * CC + c)       = h0;
        *reinterpret_cast<__half2*>(Y + base + (size_t)(r0 + 8) * CC + c) = h1;
    }
}

// ---------------------------------------------------------------------------
// Launch
// ---------------------------------------------------------------------------
extern "C" void kernel_launch(void* const* d_in, const int* in_sizes, int n_in,
                              void* d_out, int out_size)
{
    const float* x      = (const float*)d_in[0];
    const float* Wq     = (const float*)d_in[1];
    const float* Wk     = (const float*)d_in[2];
    const float* Wv     = (const float*)d_in[3];
    const float* Wp     = (const float*)d_in[4];
    const float* bp     = (const float*)d_in[5];
    const float* W1     = (const float*)d_in[6];
    const float* b1     = (const float*)d_in[7];
    const float* W2     = (const float*)d_in[8];
    const float* b2     = (const float*)d_in[9];
    const float* gamma1 = (const float*)d_in[10];
    const float* beta1  = (const float*)d_in[11];
    const float* gamma2 = (const float*)d_in[12];
    const float* beta2  = (const float*)d_in[13];
    float* out = (float*)d_out;

    __half *xn, *q, *k, *v, *y, *xn2, *hbuf;
    float  *x1;
    __half *wqkvT, *wpT, *w1T, *w2T;
    cudaGetSymbolAddress((void**)&xn,    g_xn);
    cudaGetSymbolAddress((void**)&q,     g_q);
    cudaGetSymbolAddress((void**)&k,     g_k);
    cudaGetSymbolAddress((void**)&v,     g_v);
    cudaGetSymbolAddress((void**)&y,     g_y);
    cudaGetSymbolAddress((void**)&x1,    g_x1);
    cudaGetSymbolAddress((void**)&xn2,   g_xn2);
    cudaGetSymbolAddress((void**)&hbuf,  g_h);
    cudaGetSymbolAddress((void**)&wqkvT, g_wqkvT);
    cudaGetSymbolAddress((void**)&wpT,   g_wpT);
    cudaGetSymbolAddress((void**)&w1T,   g_w1T);
    cudaGetSymbolAddress((void**)&w2T,   g_w2T);

    static int smem_set = 0;
    if (!smem_set) {
        cudaFuncSetAttribute(hgemm<0>, cudaFuncAttributeMaxDynamicSharedMemorySize, SMEM_GEMM);
        cudaFuncSetAttribute(hgemm<1>, cudaFuncAttributeMaxDynamicSharedMemorySize, SMEM_GEMM);
        cudaFuncSetAttribute(hgemm<2>, cudaFuncAttributeMaxDynamicSharedMemorySize, SMEM_GEMM);
        cudaFuncSetAttribute(hgemm<3>, cudaFuncAttributeMaxDynamicSharedMemorySize, SMEM_GEMM);
        cudaFuncSetAttribute(fattn_kernel, cudaFuncAttributeMaxDynamicSharedMemorySize, SMEM_ATTN);
        smem_set = 1;
    }

    // D^-0.5 * log2(e): softmax logits land pre-scaled for base-2 exp
    const float scale = 0.125f * 1.4426950408889634f;
    const dim3 tb(32, 8);
    const dim3 gC(CC / 128, MM / 128);       // (8, 32)
    const dim3 gF(FF / 128, MM / 128);       // (32, 32)
    const dim3 gQKV(3 * CC / 128, MM / 128); // (24, 32)

    ln_kernel<<<MM, 256>>>(x, gamma1, beta1, xn);                                        // 1
    transpose_qkv_kernel<<<dim3(CC/32, CC/32, 3), tb>>>(Wq, Wk, Wv, wqkvT);              // 2
    transpose_h_kernel<<<dim3(CC/32, CC/32), tb>>>(Wp, wpT, CC, CC);                     // 3
    hgemm<3><<<gQKV, 256, SMEM_GEMM>>>(xn, wqkvT, q, MM, CC, CC, scale, nullptr, nullptr,
                                       k, v);                                            // 4 <- profiled
    transpose_h_kernel<<<dim3(FF/32, CC/32), tb>>>(W1, w1T, CC, FF);                     // 5
    transpose_h_kernel<<<dim3(CC/32, FF/32), tb>>>(W2, w2T, FF, CC);                     // 6
    fattn_kernel<<<dim3(NN / QTILE, HH, BB), 256, SMEM_ATTN>>>(q, k, v, y);              // 7
    hgemm<1><<<gC, 256, SMEM_GEMM>>>(y, wpT, x1, MM, CC, CC, 1.0f, bp, x);               // 8
    ln_kernel<<<MM, 256>>>(x1, gamma2, beta2, xn2);                                      // 9
    hgemm<2><<<gF, 256, SMEM_GEMM>>>(xn2, w1T, hbuf, MM, FF, CC, 1.0f, b1, nullptr);     // 10
    hgemm<1><<<gC, 256, SMEM_GEMM>>>(hbuf, w2T, out, MM, CC, FF, 1.0f, b2, x1);          // 11
}